// round 5
// baseline (speedup 1.0000x reference)
#include <cuda_runtime.h>
#include <cstdint>

#define BB 16
#define CC 128
#define DD 32
#define NN 2048
#define SQRT_LOG2E 1.2011224087864498f

// ---------------- device scratch (static) ----------------
__device__ float g_qs[BB * NN * DD];   // qT[b][n][d], *sqrt(log2e), tf32-rounded
__device__ float g_v [BB * CC * NN];   // v[b][c][n], tf32-rounded
__device__ float g_rsinv[BB * NN];     // 1/rowsum

// ---------------- helpers ----------------
__device__ __forceinline__ float to_tf32(float x) {
    uint32_t u; asm("cvt.rna.tf32.f32 %0, %1;" : "=r"(u) : "f"(x));
    return __uint_as_float(u);
}
__device__ __forceinline__ float ex2f(float x) {
    float y; asm("ex2.approx.ftz.f32 %0, %1;" : "=f"(y) : "f"(x)); return y;
}
__device__ __forceinline__ void mma8(float c[4],
                                     uint32_t a0, uint32_t a1, uint32_t a2, uint32_t a3,
                                     uint32_t b0, uint32_t b1) {
    asm volatile(
        "mma.sync.aligned.m16n8k8.row.col.f32.tf32.tf32.f32 "
        "{%0,%1,%2,%3}, {%4,%5,%6,%7}, {%8,%9}, {%0,%1,%2,%3};"
        : "+f"(c[0]), "+f"(c[1]), "+f"(c[2]), "+f"(c[3])
        : "r"(a0), "r"(a1), "r"(a2), "r"(a3), "r"(b0), "r"(b1));
}
__device__ __forceinline__ uint32_t fu(float f) { return __float_as_uint(f); }
__device__ __forceinline__ uint32_t smem_u32(const void* p) {
    uint32_t a;
    asm("{ .reg .u64 t; cvta.to.shared.u64 t, %1; cvt.u32.u64 %0, t; }" : "=r"(a) : "l"(p));
    return a;
}
__device__ __forceinline__ void cpa16(uint32_t dst, const float* src) {
    asm volatile("cp.async.cg.shared.global [%0], [%1], 16;" :: "r"(dst), "l"(src));
}
#define CPA_COMMIT() asm volatile("cp.async.commit_group;" ::: "memory")
#define CPA_WAIT(n)  asm volatile("cp.async.wait_group %0;" :: "n"(n) : "memory")

// ======================================================================
// k1: q = wq@x (scaled, transposed, tf32) ; v = wv@x + bv (tf32)
// 640 threads (20 warps, 32x32 warp tiles on a 160x128 output).
// ======================================================================
__global__ __launch_bounds__(640) void k_qv(const float* __restrict__ x,
                                            const float* __restrict__ wq,
                                            const float* __restrict__ wv,
                                            const float* __restrict__ bv) {
    extern __shared__ float sm[];
    float* xT   = sm;             // 128*132  xT[n][c]
    float* ws   = sm + 16896;     // 160*132  ws[r][c]
    float* qb   = sm + 38016;     // 32*129
    float* bv_s = sm + 42144;     // 128
    const int b  = blockIdx.y;
    const int n0 = blockIdx.x * 128;
    const int tid = threadIdx.x;
    const float* xb = x + (size_t)b * CC * NN;

    for (int i = tid; i < CC * 128; i += 640) {
        int c = i >> 7, n = i & 127;
        xT[n * 132 + c] = xb[(size_t)c * NN + n0 + n];
    }
    for (int i = tid; i < 160 * 128; i += 640) {
        int r = i >> 7, c = i & 127;
        ws[r * 132 + c] = (r < DD) ? wq[r * CC + c] : wv[(r - DD) * CC + c];
    }
    if (tid < CC) bv_s[tid] = bv[tid];
    __syncthreads();

    const int w = tid >> 5, lane = tid & 31;
    const int rg = w >> 2, cg = w & 3;
    const int row0 = rg * 32, col0 = cg * 32;
    const int qr = lane >> 2, ql = lane & 3;

    float acc[2][4][4] = {};
#pragma unroll
    for (int ks = 0; ks < 16; ++ks) {
        const int k0 = ks * 8;
        uint32_t A[2][4];
#pragma unroll
        for (int mi = 0; mi < 2; ++mi) {
            int r = row0 + mi * 16 + qr;
            A[mi][0] = fu(ws[r * 132 + k0 + ql]);
            A[mi][1] = fu(ws[(r + 8) * 132 + k0 + ql]);
            A[mi][2] = fu(ws[r * 132 + k0 + 4 + ql]);
            A[mi][3] = fu(ws[(r + 8) * 132 + k0 + 4 + ql]);
        }
#pragma unroll
        for (int ni = 0; ni < 4; ++ni) {
            int cb = col0 + ni * 8 + qr;
            uint32_t b0 = fu(xT[cb * 132 + k0 + ql]);
            uint32_t b1 = fu(xT[cb * 132 + k0 + 4 + ql]);
            mma8(acc[0][ni], A[0][0], A[0][1], A[0][2], A[0][3], b0, b1);
            mma8(acc[1][ni], A[1][0], A[1][1], A[1][2], A[1][3], b0, b1);
        }
    }

    if (rg == 0) {
#pragma unroll
        for (int mi = 0; mi < 2; ++mi) {
            int d = mi * 16 + qr;
#pragma unroll
            for (int ni = 0; ni < 4; ++ni) {
                int col = col0 + ni * 8 + 2 * ql;
                qb[d * 129 + col]           = to_tf32(acc[mi][ni][0] * SQRT_LOG2E);
                qb[d * 129 + col + 1]       = to_tf32(acc[mi][ni][1] * SQRT_LOG2E);
                qb[(d + 8) * 129 + col]     = to_tf32(acc[mi][ni][2] * SQRT_LOG2E);
                qb[(d + 8) * 129 + col + 1] = to_tf32(acc[mi][ni][3] * SQRT_LOG2E);
            }
        }
    } else {
#pragma unroll
        for (int mi = 0; mi < 2; ++mi) {
            int rv = row0 - DD + mi * 16 + qr;
            float b0v = bv_s[rv], b1v = bv_s[rv + 8];
#pragma unroll
            for (int ni = 0; ni < 4; ++ni) {
                int col = col0 + ni * 8 + 2 * ql;
                float2 o0 = make_float2(to_tf32(acc[mi][ni][0] + b0v), to_tf32(acc[mi][ni][1] + b0v));
                float2 o1 = make_float2(to_tf32(acc[mi][ni][2] + b1v), to_tf32(acc[mi][ni][3] + b1v));
                *(float2*)&g_v[((size_t)b * CC + rv) * NN + n0 + col]     = o0;
                *(float2*)&g_v[((size_t)b * CC + rv + 8) * NN + n0 + col] = o1;
            }
        }
    }
    __syncthreads();
    for (int i = tid; i < 128 * DD; i += 640) {
        int n = i >> 5, d = i & 31;
        g_qs[((size_t)b * NN + n0 + n) * DD + d] = qb[d * 129 + n];
    }
}

// ======================================================================
// k2: rowsum[n] = sum_m exp2(E[n,m]); 512 threads, 2 CTAs/SM,
// double-buffered qm via cp.async.
// ======================================================================
__global__ __launch_bounds__(512, 2) void k_rowsum() {
    extern __shared__ float sm[];
    float* red  = sm;              // 128
    float* qn_s = sm + 128;        // 128*36
    float* qm0  = sm + 128 + 4608;
    float* qm1  = qm0 + 4608;

    const int tid = threadIdx.x, w = tid >> 5, lane = tid & 31;
    const int row0 = (w & 3) * 32, col0 = (w >> 2) * 32;
    const int qr = lane >> 2, ql = lane & 3;
    const int b = blockIdx.y, n0 = blockIdx.x * 128;
    const uint32_t qm0u = smem_u32(qm0), qm1u = smem_u32(qm1);

    if (tid < 128) red[tid] = 0.f;
    for (int i = tid; i < 128 * DD; i += 512) {
        int r = i >> 5, d = i & 31;
        qn_s[r * 36 + d] = g_qs[((size_t)b * NN + n0 + r) * DD + d];
    }
#pragma unroll
    for (int k = 0; k < 2; ++k) {
        int idx4 = tid + k * 512;
        int r = idx4 >> 3, d4 = (idx4 & 7) << 2;
        cpa16(qm0u + (r * 36 + d4) * 4, &g_qs[((size_t)b * NN + r) * DD + d4]);
    }
    CPA_COMMIT();

    float racc[2][2] = {};
    for (int mt = 0; mt < NN / 128; ++mt) {
        const float* qm = (mt & 1) ? qm1 : qm0;
        const uint32_t qmnu = (mt & 1) ? qm0u : qm1u;
        CPA_WAIT(0);
        __syncthreads();
        if (mt + 1 < NN / 128) {
#pragma unroll
            for (int k = 0; k < 2; ++k) {
                int idx4 = tid + k * 512;
                int r = idx4 >> 3, d4 = (idx4 & 7) << 2;
                cpa16(qmnu + (r * 36 + d4) * 4,
                      &g_qs[((size_t)b * NN + (mt + 1) * 128 + r) * DD + d4]);
            }
            CPA_COMMIT();
        }

        float e[2][4][4] = {};
#pragma unroll
        for (int ks = 0; ks < 4; ++ks) {
            const int k0 = ks * 8;
            uint32_t A[2][4];
#pragma unroll
            for (int mi = 0; mi < 2; ++mi) {
                int r = row0 + mi * 16 + qr;
                A[mi][0] = fu(qn_s[r * 36 + k0 + ql]);
                A[mi][1] = fu(qn_s[(r + 8) * 36 + k0 + ql]);
                A[mi][2] = fu(qn_s[r * 36 + k0 + 4 + ql]);
                A[mi][3] = fu(qn_s[(r + 8) * 36 + k0 + 4 + ql]);
            }
#pragma unroll
            for (int ni = 0; ni < 4; ++ni) {
                int cb = col0 + ni * 8 + qr;
                uint32_t b0 = fu(qm[cb * 36 + k0 + ql]);
                uint32_t b1 = fu(qm[cb * 36 + k0 + 4 + ql]);
                mma8(e[0][ni], A[0][0], A[0][1], A[0][2], A[0][3], b0, b1);
                mma8(e[1][ni], A[1][0], A[1][1], A[1][2], A[1][3], b0, b1);
            }
        }
#pragma unroll
        for (int mi = 0; mi < 2; ++mi)
#pragma unroll
            for (int ni = 0; ni < 4; ++ni) {
                racc[mi][0] += ex2f(e[mi][ni][0]) + ex2f(e[mi][ni][1]);
                racc[mi][1] += ex2f(e[mi][ni][2]) + ex2f(e[mi][ni][3]);
            }
    }

#pragma unroll
    for (int mi = 0; mi < 2; ++mi)
#pragma unroll
        for (int h = 0; h < 2; ++h) {
            float v = racc[mi][h];
            v += __shfl_xor_sync(0xffffffffu, v, 1);
            v += __shfl_xor_sync(0xffffffffu, v, 2);
            racc[mi][h] = v;
        }
    if (ql == 0) {
        atomicAdd(&red[row0 + qr],          racc[0][0]);
        atomicAdd(&red[row0 + qr + 8],      racc[0][1]);
        atomicAdd(&red[row0 + 16 + qr],     racc[1][0]);
        atomicAdd(&red[row0 + 16 + qr + 8], racc[1][1]);
    }
    __syncthreads();
    if (tid < 128) g_rsinv[(size_t)b * NN + n0 + tid] = 1.0f / red[tid];
}

// ======================================================================
// k3: fused attention + epilogue. 256 threads, 3 CTAs/SM.
// m-tile 64, n-tile 64, grid (32, 16).
// E warps: 4 n-groups x 2 m-groups (16x32); Y warps: 4 c-groups x 2 m-groups (32x32).
// smem floats:
//   csum 0..64, cinv 64..128, A_s 128..256, S_s 256..384, rsinv 384..448
//   qm 448..2752 (64x36), qn 2752..5056, vs 5056..13760 (128x68),
//   pT 13760..18112 (64x68). Epilogue xmT (64x132) overlays vs.
// ======================================================================
__global__ __launch_bounds__(256, 3) void k_attn(const float* __restrict__ x,
                                                 const float* __restrict__ wt,
                                                 const float* __restrict__ bt,
                                                 const float* __restrict__ gamma,
                                                 const float* __restrict__ beta,
                                                 const float* __restrict__ mean,
                                                 const float* __restrict__ var,
                                                 float* __restrict__ out) {
    extern __shared__ float sm[];
    float* csum_s  = sm;
    float* cinv_s  = sm + 64;
    float* A_s     = sm + 128;
    float* S_s     = sm + 256;
    float* rsinv_s = sm + 384;
    float* qm_s    = sm + 448;
    float* qn_s    = sm + 2752;
    float* vs      = sm + 5056;
    float* pT      = sm + 13760;
    float* xmT     = vs;            // epilogue overlay

    const int tid = threadIdx.x, w = tid >> 5, lane = tid & 31;
    const int qr = lane >> 2, ql = lane & 3;
    const int rE = (w >> 1) * 16;   // E n-row group
    const int cW = (w & 1) * 32;    // m-col group (shared by E and Y)
    const int rY = (w >> 1) * 32;   // Y c-row group
    const int b = blockIdx.y, m0 = blockIdx.x * 64;
    const uint32_t qn_u = smem_u32(qn_s), vs_u = smem_u32(vs);

    if (tid < 64) csum_s[tid] = 0.f;
    if (tid >= 64 && tid < 192) {
        int c = tid - 64;
        float A = gamma[c] * rsqrtf(var[c] + 1e-5f);
        A_s[c] = A;
        S_s[c] = beta[c] + (bt[c] - mean[c]) * A;
    }
    for (int i = tid; i < 64 * DD; i += 256) {
        int r = i >> 5, d = i & 31;
        qm_s[r * 36 + d] = g_qs[((size_t)b * NN + m0 + r) * DD + d];
    }
    // prologue: prefetch qn(0), vs(0)
    for (int idx4 = tid; idx4 < 512; idx4 += 256) {
        int r = idx4 >> 3, d4 = (idx4 & 7) << 2;
        cpa16(qn_u + (r * 36 + d4) * 4, &g_qs[((size_t)b * NN + r) * DD + d4]);
    }
    CPA_COMMIT();
#pragma unroll
    for (int k = 0; k < 8; ++k) {
        int idx4 = tid + k * 256;
        int c = idx4 >> 4, n4 = (idx4 & 15) << 2;
        cpa16(vs_u + (c * 68 + n4) * 4, &g_v[((size_t)b * CC + c) * NN + n4]);
    }
    CPA_COMMIT();

    float yacc[2][4][4] = {};
    float csum[8] = {};

    for (int nt = 0; nt < NN / 64; ++nt) {
        const int nb = nt * 64;
        if (tid < 64) rsinv_s[tid] = g_rsinv[(size_t)b * NN + nb + tid];
        CPA_WAIT(1);             // qn(nt) arrived
        __syncthreads();         // qn + rsinv visible

        // ---- E = qn . qm^T (16x32 per warp), K=32 ----
        float e[4][4] = {};
#pragma unroll
        for (int ks = 0; ks < 4; ++ks) {
            const int k0 = ks * 8;
            int r = rE + qr;
            uint32_t a0 = fu(qn_s[r * 36 + k0 + ql]);
            uint32_t a1 = fu(qn_s[(r + 8) * 36 + k0 + ql]);
            uint32_t a2 = fu(qn_s[r * 36 + k0 + 4 + ql]);
            uint32_t a3 = fu(qn_s[(r + 8) * 36 + k0 + 4 + ql]);
#pragma unroll
            for (int ni = 0; ni < 4; ++ni) {
                int cb = cW + ni * 8 + qr;
                uint32_t b0 = fu(qm_s[cb * 36 + k0 + ql]);
                uint32_t b1 = fu(qm_s[cb * 36 + k0 + 4 + ql]);
                mma8(e[ni], a0, a1, a2, a3, b0, b1);
            }
        }

        // ---- p = ex2(e)*rsinv; csum; pT[m][n] ----
        {
            int r0 = rE + qr, r1 = r0 + 8;
            float ri0 = rsinv_s[r0], ri1 = rsinv_s[r1];
#pragma unroll
            for (int ni = 0; ni < 4; ++ni) {
                int col = cW + ni * 8 + 2 * ql;
                float p00 = ex2f(e[ni][0]) * ri0;
                float p01 = ex2f(e[ni][1]) * ri0;
                float p10 = ex2f(e[ni][2]) * ri1;
                float p11 = ex2f(e[ni][3]) * ri1;
                csum[ni * 2]     += p00 + p10;
                csum[ni * 2 + 1] += p01 + p11;
                pT[col * 68 + r0]       = to_tf32(p00);
                pT[(col + 1) * 68 + r0] = to_tf32(p01);
                pT[col * 68 + r1]       = to_tf32(p10);
                pT[(col + 1) * 68 + r1] = to_tf32(p11);
            }
        }
        CPA_WAIT(0);             // vs(nt) arrived
        __syncthreads();         // pT + vs visible, qn reads done

        if (nt + 1 < NN / 64) {  // prefetch qn(nt+1) overlapping Y-mma
            for (int idx4 = tid; idx4 < 512; idx4 += 256) {
                int r = idx4 >> 3, d4 = (idx4 & 7) << 2;
                cpa16(qn_u + (r * 36 + d4) * 4,
                      &g_qs[((size_t)b * NN + nb + 64 + r) * DD + d4]);
            }
            CPA_COMMIT();
        }

        // ---- Y += v @ p (32x32 per warp), K=64 ----
#pragma unroll
        for (int ks = 0; ks < 8; ++ks) {
            const int k0 = ks * 8;
            uint32_t A[2][4];
#pragma unroll
            for (int mi = 0; mi < 2; ++mi) {
                int r = rY + mi * 16 + qr;
                A[mi][0] = fu(vs[r * 68 + k0 + ql]);
                A[mi][1] = fu(vs[(r + 8) * 68 + k0 + ql]);
                A[mi][2] = fu(vs[r * 68 + k0 + 4 + ql]);
                A[mi][3] = fu(vs[(r + 8) * 68 + k0 + 4 + ql]);
            }
#pragma unroll
            for (int ni = 0; ni < 4; ++ni) {
                int cb = cW + ni * 8 + qr;
                uint32_t b0 = fu(pT[cb * 68 + k0 + ql]);
                uint32_t b1 = fu(pT[cb * 68 + k0 + 4 + ql]);
                mma8(yacc[0][ni], A[0][0], A[0][1], A[0][2], A[0][3], b0, b1);
                mma8(yacc[1][ni], A[1][0], A[1][1], A[1][2], A[1][3], b0, b1);
            }
        }
        __syncthreads();         // vs/pT reads done
        if (nt + 1 < NN / 64) {  // prefetch vs(nt+1) overlapping next E+exp
#pragma unroll
            for (int k = 0; k < 8; ++k) {
                int idx4 = tid + k * 256;
                int c = idx4 >> 4, n4 = (idx4 & 15) << 2;
                cpa16(vs_u + (c * 68 + n4) * 4,
                      &g_v[((size_t)b * CC + c) * NN + nb + 64 + n4]);
            }
            CPA_COMMIT();
        }
    }

    // ---------------- epilogue ----------------
#pragma unroll
    for (int i = 0; i < 8; ++i) {
        float v = csum[i];
        v += __shfl_xor_sync(0xffffffffu, v, 4);
        v += __shfl_xor_sync(0xffffffffu, v, 8);
        v += __shfl_xor_sync(0xffffffffu, v, 16);
        if (qr == 0) atomicAdd(&csum_s[cW + (i >> 1) * 8 + 2 * ql + (i & 1)], v);
    }
    __syncthreads();
    if (tid < 64) cinv_s[tid] = 1.0f / (1e-9f + csum_s[tid]);
    __syncthreads();

    // xmT[m][c] = x - Y*cinv (transposed into vs region, stride 132)
    const float* xb = x + ((size_t)b * CC) * NN + m0;
#pragma unroll
    for (int mi = 0; mi < 2; ++mi) {
        int r = rY + mi * 16 + qr;
#pragma unroll
        for (int ni = 0; ni < 4; ++ni) {
            int col = cW + ni * 8 + 2 * ql;
            float2 x0 = __ldg((const float2*)&xb[(size_t)r * NN + col]);
            float2 x1 = __ldg((const float2*)&xb[(size_t)(r + 8) * NN + col]);
            float ci0 = cinv_s[col], ci1 = cinv_s[col + 1];
            xmT[col * 132 + r]           = to_tf32(x0.x - yacc[mi][ni][0] * ci0);
            xmT[(col + 1) * 132 + r]     = to_tf32(x0.y - yacc[mi][ni][1] * ci1);
            xmT[col * 132 + r + 8]       = to_tf32(x1.x - yacc[mi][ni][2] * ci0);
            xmT[(col + 1) * 132 + r + 8] = to_tf32(x1.y - yacc[mi][ni][3] * ci1);
        }
    }
    __syncthreads();

    // t = wt @ xm  (A-fragments straight from gmem; wt is L2-resident)
    float tacc[2][4][4] = {};
#pragma unroll
    for (int ks = 0; ks < 16; ++ks) {
        const int k0 = ks * 8;
        uint32_t A[2][4];
#pragma unroll
        for (int mi = 0; mi < 2; ++mi) {
            int r = rY + mi * 16 + qr;
            A[mi][0] = fu(to_tf32(__ldg(&wt[r * CC + k0 + ql])));
            A[mi][1] = fu(to_tf32(__ldg(&wt[(r + 8) * CC + k0 + ql])));
            A[mi][2] = fu(to_tf32(__ldg(&wt[r * CC + k0 + 4 + ql])));
            A[mi][3] = fu(to_tf32(__ldg(&wt[(r + 8) * CC + k0 + 4 + ql])));
        }
#pragma unroll
        for (int ni = 0; ni < 4; ++ni) {
            int cb = cW + ni * 8 + qr;
            uint32_t b0 = fu(xmT[cb * 132 + k0 + ql]);
            uint32_t b1 = fu(xmT[cb * 132 + k0 + 4 + ql]);
            mma8(tacc[0][ni], A[0][0], A[0][1], A[0][2], A[0][3], b0, b1);
            mma8(tacc[1][ni], A[1][0], A[1][1], A[1][2], A[1][3], b0, b1);
        }
    }

    // out = x + relu(t*A + S)
#pragma unroll
    for (int mi = 0; mi < 2; ++mi) {
        int r = rY + mi * 16 + qr;
        float a0 = A_s[r], s0 = S_s[r];
        float a1 = A_s[r + 8], s1 = S_s[r + 8];
#pragma unroll
        for (int ni = 0; ni < 4; ++ni) {
            int col = cW + ni * 8 + 2 * ql;
            float2 x0 = __ldg((const float2*)&xb[(size_t)r * NN + col]);
            float2 x1 = __ldg((const float2*)&xb[(size_t)(r + 8) * NN + col]);
            float2 o0, o1;
            o0.x = x0.x + fmaxf(fmaf(tacc[mi][ni][0], a0, s0), 0.f);
            o0.y = x0.y + fmaxf(fmaf(tacc[mi][ni][1], a0, s0), 0.f);
            o1.x = x1.x + fmaxf(fmaf(tacc[mi][ni][2], a1, s1), 0.f);
            o1.y = x1.y + fmaxf(fmaf(tacc[mi][ni][3], a1, s1), 0.f);
            *(float2*)&out[((size_t)b * CC + r) * NN + m0 + col]     = o0;
            *(float2*)&out[((size_t)b * CC + r + 8) * NN + m0 + col] = o1;
        }
    }
}

// ======================================================================
extern "C" void kernel_launch(void* const* d_in, const int* in_sizes, int n_in,
                              void* d_out, int out_size) {
    const float* x     = (const float*)d_in[0];
    const float* wq    = (const float*)d_in[1];
    const float* wv    = (const float*)d_in[2];
    const float* bv    = (const float*)d_in[3];
    const float* wt    = (const float*)d_in[4];
    const float* bt    = (const float*)d_in[5];
    const float* gamma = (const float*)d_in[6];
    const float* beta  = (const float*)d_in[7];
    const float* mean  = (const float*)d_in[8];
    const float* var   = (const float*)d_in[9];
    float* out = (float*)d_out;

    const int S1 = (16896 + 21120 + 4128 + 128) * 4;   // 169088
    const int S2 = (128 + 3 * 4608) * 4;               // 55808
    const int S3 = 18112 * 4;                          // 72448

    cudaFuncSetAttribute(k_qv,     cudaFuncAttributeMaxDynamicSharedMemorySize, S1);
    cudaFuncSetAttribute(k_rowsum, cudaFuncAttributeMaxDynamicSharedMemorySize, S2);
    cudaFuncSetAttribute(k_attn,   cudaFuncAttributeMaxDynamicSharedMemorySize, S3);

    k_qv<<<dim3(16, 16), 640, S1>>>(x, wq, wv, bv);
    k_rowsum<<<dim3(16, 16), 512, S2>>>();
    k_attn<<<dim3(32, 16), 256, S3>>>(x, wt, bt, gamma, beta, mean, var, out);
}

// round 6
// speedup vs baseline: 1.3742x; 1.3742x over previous
#include <cuda_runtime.h>
#include <cuda_fp16.h>
#include <cstdint>

#define BB 16
#define CC 128
#define DD 32
#define NN 2048
#define SQRT_LOG2E 1.2011224087864498f

// ---------------- device scratch (static) ----------------
__device__ float  g_qs[BB * NN * DD];   // qT[b][n][d], *sqrt(log2e), tf32-rounded
__device__ __half g_v [BB * CC * NN];   // v[b][c][n], fp16
__device__ float  g_rsinv[BB * NN];     // 1/rowsum

// ---------------- helpers ----------------
__device__ __forceinline__ float to_tf32(float x) {
    uint32_t u; asm("cvt.rna.tf32.f32 %0, %1;" : "=r"(u) : "f"(x));
    return __uint_as_float(u);
}
__device__ __forceinline__ float ex2f(float x) {
    float y; asm("ex2.approx.ftz.f32 %0, %1;" : "=f"(y) : "f"(x)); return y;
}
__device__ __forceinline__ void mma8(float c[4],
                                     uint32_t a0, uint32_t a1, uint32_t a2, uint32_t a3,
                                     uint32_t b0, uint32_t b1) {
    asm volatile(
        "mma.sync.aligned.m16n8k8.row.col.f32.tf32.tf32.f32 "
        "{%0,%1,%2,%3}, {%4,%5,%6,%7}, {%8,%9}, {%0,%1,%2,%3};"
        : "+f"(c[0]), "+f"(c[1]), "+f"(c[2]), "+f"(c[3])
        : "r"(a0), "r"(a1), "r"(a2), "r"(a3), "r"(b0), "r"(b1));
}
__device__ __forceinline__ void mma16h(float c[4],
                                       uint32_t a0, uint32_t a1, uint32_t a2, uint32_t a3,
                                       uint32_t b0, uint32_t b1) {
    asm volatile(
        "mma.sync.aligned.m16n8k16.row.col.f32.f16.f16.f32 "
        "{%0,%1,%2,%3}, {%4,%5,%6,%7}, {%8,%9}, {%0,%1,%2,%3};"
        : "+f"(c[0]), "+f"(c[1]), "+f"(c[2]), "+f"(c[3])
        : "r"(a0), "r"(a1), "r"(a2), "r"(a3), "r"(b0), "r"(b1));
}
__device__ __forceinline__ uint32_t fu(float f) { return __float_as_uint(f); }
__device__ __forceinline__ uint32_t smem_u32(const void* p) {
    uint32_t a;
    asm("{ .reg .u64 t; cvta.to.shared.u64 t, %1; cvt.u32.u64 %0, t; }" : "=r"(a) : "l"(p));
    return a;
}
__device__ __forceinline__ void cpa16(uint32_t dst, const void* src) {
    asm volatile("cp.async.cg.shared.global [%0], [%1], 16;" :: "r"(dst), "l"(src));
}
#define CPA_COMMIT() asm volatile("cp.async.commit_group;" ::: "memory")
#define CPA_WAIT(n)  asm volatile("cp.async.wait_group %0;" :: "n"(n) : "memory")

// ======================================================================
// k1: q = wq@x (scaled, transposed, tf32) ; v = wv@x + bv (fp16)
// 640 threads (20 warps, 32x32 warp tiles on a 160x128 output).
// ======================================================================
__global__ __launch_bounds__(640) void k_qv(const float* __restrict__ x,
                                            const float* __restrict__ wq,
                                            const float* __restrict__ wv,
                                            const float* __restrict__ bv) {
    extern __shared__ float sm[];
    float* xT   = sm;             // 128*132  xT[n][c]
    float* ws   = sm + 16896;     // 160*132  ws[r][c]
    float* qb   = sm + 38016;     // 32*129
    float* bv_s = sm + 42144;     // 128
    const int b  = blockIdx.y;
    const int n0 = blockIdx.x * 128;
    const int tid = threadIdx.x;
    const float* xb = x + (size_t)b * CC * NN;

    for (int i = tid; i < CC * 128; i += 640) {
        int c = i >> 7, n = i & 127;
        xT[n * 132 + c] = xb[(size_t)c * NN + n0 + n];
    }
    for (int i = tid; i < 160 * 128; i += 640) {
        int r = i >> 7, c = i & 127;
        ws[r * 132 + c] = (r < DD) ? wq[r * CC + c] : wv[(r - DD) * CC + c];
    }
    if (tid < CC) bv_s[tid] = bv[tid];
    __syncthreads();

    const int w = tid >> 5, lane = tid & 31;
    const int rg = w >> 2, cg = w & 3;
    const int row0 = rg * 32, col0 = cg * 32;
    const int qr = lane >> 2, ql = lane & 3;

    float acc[2][4][4] = {};
#pragma unroll
    for (int ks = 0; ks < 16; ++ks) {
        const int k0 = ks * 8;
        uint32_t A[2][4];
#pragma unroll
        for (int mi = 0; mi < 2; ++mi) {
            int r = row0 + mi * 16 + qr;
            A[mi][0] = fu(ws[r * 132 + k0 + ql]);
            A[mi][1] = fu(ws[(r + 8) * 132 + k0 + ql]);
            A[mi][2] = fu(ws[r * 132 + k0 + 4 + ql]);
            A[mi][3] = fu(ws[(r + 8) * 132 + k0 + 4 + ql]);
        }
#pragma unroll
        for (int ni = 0; ni < 4; ++ni) {
            int cb = col0 + ni * 8 + qr;
            uint32_t b0 = fu(xT[cb * 132 + k0 + ql]);
            uint32_t b1 = fu(xT[cb * 132 + k0 + 4 + ql]);
            mma8(acc[0][ni], A[0][0], A[0][1], A[0][2], A[0][3], b0, b1);
            mma8(acc[1][ni], A[1][0], A[1][1], A[1][2], A[1][3], b0, b1);
        }
    }

    if (rg == 0) {
#pragma unroll
        for (int mi = 0; mi < 2; ++mi) {
            int d = mi * 16 + qr;
#pragma unroll
            for (int ni = 0; ni < 4; ++ni) {
                int col = col0 + ni * 8 + 2 * ql;
                qb[d * 129 + col]           = to_tf32(acc[mi][ni][0] * SQRT_LOG2E);
                qb[d * 129 + col + 1]       = to_tf32(acc[mi][ni][1] * SQRT_LOG2E);
                qb[(d + 8) * 129 + col]     = to_tf32(acc[mi][ni][2] * SQRT_LOG2E);
                qb[(d + 8) * 129 + col + 1] = to_tf32(acc[mi][ni][3] * SQRT_LOG2E);
            }
        }
    } else {
#pragma unroll
        for (int mi = 0; mi < 2; ++mi) {
            int rv = row0 - DD + mi * 16 + qr;
            float b0v = bv_s[rv], b1v = bv_s[rv + 8];
#pragma unroll
            for (int ni = 0; ni < 4; ++ni) {
                int col = col0 + ni * 8 + 2 * ql;
                *(half2*)&g_v[((size_t)b * CC + rv) * NN + n0 + col] =
                    __floats2half2_rn(acc[mi][ni][0] + b0v, acc[mi][ni][1] + b0v);
                *(half2*)&g_v[((size_t)b * CC + rv + 8) * NN + n0 + col] =
                    __floats2half2_rn(acc[mi][ni][2] + b1v, acc[mi][ni][3] + b1v);
            }
        }
    }
    __syncthreads();
    for (int i = tid; i < 128 * DD; i += 640) {
        int n = i >> 5, d = i & 31;
        g_qs[((size_t)b * NN + n0 + n) * DD + d] = qb[d * 129 + n];
    }
}

// ======================================================================
// k2: rowsum[n] = sum_m exp2(E[n,m]); 512 threads, 2 CTAs/SM,
// double-buffered qm via cp.async.
// ======================================================================
__global__ __launch_bounds__(512, 2) void k_rowsum() {
    extern __shared__ float sm[];
    float* red  = sm;              // 128
    float* qn_s = sm + 128;        // 128*36
    float* qm0  = sm + 128 + 4608;
    float* qm1  = qm0 + 4608;

    const int tid = threadIdx.x, w = tid >> 5, lane = tid & 31;
    const int row0 = (w & 3) * 32, col0 = (w >> 2) * 32;
    const int qr = lane >> 2, ql = lane & 3;
    const int b = blockIdx.y, n0 = blockIdx.x * 128;
    const uint32_t qm0u = smem_u32(qm0), qm1u = smem_u32(qm1);

    if (tid < 128) red[tid] = 0.f;
    for (int i = tid; i < 128 * DD; i += 512) {
        int r = i >> 5, d = i & 31;
        qn_s[r * 36 + d] = g_qs[((size_t)b * NN + n0 + r) * DD + d];
    }
#pragma unroll
    for (int k = 0; k < 2; ++k) {
        int idx4 = tid + k * 512;
        int r = idx4 >> 3, d4 = (idx4 & 7) << 2;
        cpa16(qm0u + (r * 36 + d4) * 4, &g_qs[((size_t)b * NN + r) * DD + d4]);
    }
    CPA_COMMIT();

    float racc[2][2] = {};
    for (int mt = 0; mt < NN / 128; ++mt) {
        const float* qm = (mt & 1) ? qm1 : qm0;
        const uint32_t qmnu = (mt & 1) ? qm0u : qm1u;
        CPA_WAIT(0);
        __syncthreads();
        if (mt + 1 < NN / 128) {
#pragma unroll
            for (int k = 0; k < 2; ++k) {
                int idx4 = tid + k * 512;
                int r = idx4 >> 3, d4 = (idx4 & 7) << 2;
                cpa16(qmnu + (r * 36 + d4) * 4,
                      &g_qs[((size_t)b * NN + (mt + 1) * 128 + r) * DD + d4]);
            }
            CPA_COMMIT();
        }

        float e[2][4][4] = {};
#pragma unroll
        for (int ks = 0; ks < 4; ++ks) {
            const int k0 = ks * 8;
            uint32_t A[2][4];
#pragma unroll
            for (int mi = 0; mi < 2; ++mi) {
                int r = row0 + mi * 16 + qr;
                A[mi][0] = fu(qn_s[r * 36 + k0 + ql]);
                A[mi][1] = fu(qn_s[(r + 8) * 36 + k0 + ql]);
                A[mi][2] = fu(qn_s[r * 36 + k0 + 4 + ql]);
                A[mi][3] = fu(qn_s[(r + 8) * 36 + k0 + 4 + ql]);
            }
#pragma unroll
            for (int ni = 0; ni < 4; ++ni) {
                int cb = col0 + ni * 8 + qr;
                uint32_t b0 = fu(qm[cb * 36 + k0 + ql]);
                uint32_t b1 = fu(qm[cb * 36 + k0 + 4 + ql]);
                mma8(e[0][ni], A[0][0], A[0][1], A[0][2], A[0][3], b0, b1);
                mma8(e[1][ni], A[1][0], A[1][1], A[1][2], A[1][3], b0, b1);
            }
        }
#pragma unroll
        for (int mi = 0; mi < 2; ++mi)
#pragma unroll
            for (int ni = 0; ni < 4; ++ni) {
                racc[mi][0] += ex2f(e[mi][ni][0]) + ex2f(e[mi][ni][1]);
                racc[mi][1] += ex2f(e[mi][ni][2]) + ex2f(e[mi][ni][3]);
            }
    }

#pragma unroll
    for (int mi = 0; mi < 2; ++mi)
#pragma unroll
        for (int h = 0; h < 2; ++h) {
            float v = racc[mi][h];
            v += __shfl_xor_sync(0xffffffffu, v, 1);
            v += __shfl_xor_sync(0xffffffffu, v, 2);
            racc[mi][h] = v;
        }
    if (ql == 0) {
        atomicAdd(&red[row0 + qr],          racc[0][0]);
        atomicAdd(&red[row0 + qr + 8],      racc[0][1]);
        atomicAdd(&red[row0 + 16 + qr],     racc[1][0]);
        atomicAdd(&red[row0 + 16 + qr + 8], racc[1][1]);
    }
    __syncthreads();
    if (tid < 128) g_rsinv[(size_t)b * NN + n0 + tid] = 1.0f / red[tid];
}

// ======================================================================
// k3: fused attention + epilogue. 512 threads, 128x128 tiles (R4 shape),
// fp16 v/p (Y via mma.m16n8k16.f16), cp.async pipelined staging.
// smem bytes:
//   [0..2560)        csum(128f) cinv(128f) A_s(128f) S_s(128f) rsinv(128f)
//   [2560..21
//   qm_s @ 2560  (4608 f = 18432 B)
//   qn_s @ 20992 (18432 B)
//   vs_h @ 39424 (128x136 half = 34816 B)   } epilogue overlay:
//   pT_h @ 74240 (34816 B)                  } xmT fp32 128x132 @ 39424
//   total 109056 B
// ======================================================================
__global__ __launch_bounds__(512, 1) void k_attn(const float* __restrict__ x,
                                                 const float* __restrict__ wt,
                                                 const float* __restrict__ bt,
                                                 const float* __restrict__ gamma,
                                                 const float* __restrict__ beta,
                                                 const float* __restrict__ mean,
                                                 const float* __restrict__ var,
                                                 float* __restrict__ out) {
    extern __shared__ float sm[];
    char* smc = (char*)sm;
    float* csum_s  = sm;            // 128
    float* cinv_s  = sm + 128;
    float* A_s     = sm + 256;
    float* S_s     = sm + 384;
    float* rsinv_s = sm + 512;
    float* qm_s    = sm + 640;      // stride 36
    float* qn_s    = sm + 5248;     // stride 36
    __half* vs_h   = (__half*)(smc + 39424);   // stride 136
    __half* pT_h   = (__half*)(smc + 74240);   // stride 136
    float*  xmT    = (float*)(smc + 39424);    // epilogue overlay, stride 132

    const int tid = threadIdx.x, w = tid >> 5, lane = tid & 31;
    const int row0 = (w & 3) * 32, col0 = (w >> 2) * 32;
    const int qr = lane >> 2, ql = lane & 3;
    const int b = blockIdx.y, m0 = blockIdx.x * 128;
    const uint32_t qn_u = smem_u32(qn_s), vs_u = smem_u32(vs_h);

    if (tid < 128) {
        csum_s[tid] = 0.f;
        float A = gamma[tid] * rsqrtf(var[tid] + 1e-5f);
        A_s[tid] = A;
        S_s[tid] = beta[tid] + (bt[tid] - mean[tid]) * A;
    }
    for (int i = tid; i < 128 * DD; i += 512) {
        int r = i >> 5, d = i & 31;
        qm_s[r * 36 + d] = g_qs[((size_t)b * NN + m0 + r) * DD + d];
    }
    // prologue prefetch: qn(0) group, vs(0) group
#pragma unroll
    for (int k = 0; k < 2; ++k) {
        int idx4 = tid + k * 512;
        int r = idx4 >> 3, d4 = (idx4 & 7) << 2;
        cpa16(qn_u + (r * 36 + d4) * 4, &g_qs[((size_t)b * NN + r) * DD + d4]);
    }
    CPA_COMMIT();
#pragma unroll
    for (int k = 0; k < 4; ++k) {
        int idx8 = tid + k * 512;        // 2048 chunks of 8 halves
        int c = idx8 >> 4, j = (idx8 & 15) << 3;
        cpa16(vs_u + (c * 136 + j) * 2, &g_v[((size_t)b * CC + c) * NN + j]);
    }
    CPA_COMMIT();

    float yacc[2][4][4] = {};
    float csum[8] = {};

    for (int nt = 0; nt < NN / 128; ++nt) {
        const int nb = nt * 128;
        if (tid < 128) rsinv_s[tid] = g_rsinv[(size_t)b * NN + nb + tid];
        CPA_WAIT(1);                 // qn(nt) ready
        __syncthreads();

        // ---- E = qn . qm^T (tf32) ----
        float e[2][4][4] = {};
#pragma unroll
        for (int ks = 0; ks < 4; ++ks) {
            const int k0 = ks * 8;
            uint32_t A[2][4];
#pragma unroll
            for (int mi = 0; mi < 2; ++mi) {
                int r = row0 + mi * 16 + qr;
                A[mi][0] = fu(qn_s[r * 36 + k0 + ql]);
                A[mi][1] = fu(qn_s[(r + 8) * 36 + k0 + ql]);
                A[mi][2] = fu(qn_s[r * 36 + k0 + 4 + ql]);
                A[mi][3] = fu(qn_s[(r + 8) * 36 + k0 + 4 + ql]);
            }
#pragma unroll
            for (int ni = 0; ni < 4; ++ni) {
                int cb = col0 + ni * 8 + qr;
                uint32_t b0 = fu(qm_s[cb * 36 + k0 + ql]);
                uint32_t b1 = fu(qm_s[cb * 36 + k0 + 4 + ql]);
                mma8(e[0][ni], A[0][0], A[0][1], A[0][2], A[0][3], b0, b1);
                mma8(e[1][ni], A[1][0], A[1][1], A[1][2], A[1][3], b0, b1);
            }
        }

        // ---- p = ex2(e)*rsinv; csum; pT[m][n] (fp16) ----
#pragma unroll
        for (int mi = 0; mi < 2; ++mi) {
            int r = row0 + mi * 16 + qr;
            float ri0 = rsinv_s[r], ri1 = rsinv_s[r + 8];
#pragma unroll
            for (int ni = 0; ni < 4; ++ni) {
                int col = col0 + ni * 8 + 2 * ql;
                float p00 = ex2f(e[mi][ni][0]) * ri0;
                float p01 = ex2f(e[mi][ni][1]) * ri0;
                float p10 = ex2f(e[mi][ni][2]) * ri1;
                float p11 = ex2f(e[mi][ni][3]) * ri1;
                csum[ni * 2]     += p00 + p10;
                csum[ni * 2 + 1] += p01 + p11;
                pT_h[col * 136 + r]           = __float2half_rn(p00);
                pT_h[(col + 1) * 136 + r]     = __float2half_rn(p01);
                pT_h[col * 136 + r + 8]       = __float2half_rn(p10);
                pT_h[(col + 1) * 136 + r + 8] = __float2half_rn(p11);
            }
        }
        CPA_WAIT(0);                 // vs(nt) ready
        __syncthreads();             // pT visible; qn reads done

        if (nt + 1 < NN / 128) {     // prefetch qn(nt+1) during Y-mma
#pragma unroll
            for (int k = 0; k < 2; ++k) {
                int idx4 = tid + k * 512;
                int r = idx4 >> 3, d4 = (idx4 & 7) << 2;
                cpa16(qn_u + (r * 36 + d4) * 4,
                      &g_qs[((size_t)b * NN + nb + 128 + r) * DD + d4]);
            }
            CPA_COMMIT();
        }

        // ---- Y += v @ p  (fp16, K=128, 8 k16-steps) ----
#pragma unroll
        for (int ks = 0; ks < 8; ++ks) {
            const int k0 = ks * 16;
            uint32_t A[2][4];
#pragma unroll
            for (int mi = 0; mi < 2; ++mi) {
                int r = row0 + mi * 16 + qr;
                A[mi][0] = *(const uint32_t*)&vs_h[r * 136 + k0 + 2 * ql];
                A[mi][1] = *(const uint32_t*)&vs_h[(r + 8) * 136 + k0 + 2 * ql];
                A[mi][2] = *(const uint32_t*)&vs_h[r * 136 + k0 + 2 * ql + 8];
                A[mi][3] = *(const uint32_t*)&vs_h[(r + 8) * 136 + k0 + 2 * ql + 8];
            }
#pragma unroll
            for (int ni = 0; ni < 4; ++ni) {
                int cb = col0 + ni * 8 + qr;
                uint32_t b0 = *(const uint32_t*)&pT_h[cb * 136 + k0 + 2 * ql];
                uint32_t b1 = *(const uint32_t*)&pT_h[cb * 136 + k0 + 2 * ql + 8];
                mma16h(yacc[0][ni], A[0][0], A[0][1], A[0][2], A[0][3], b0, b1);
                mma16h(yacc[1][ni], A[1][0], A[1][1], A[1][2], A[1][3], b0, b1);
            }
        }
        __syncthreads();             // vs/pT reads done
        if (nt + 1 < NN / 128) {     // prefetch vs(nt+1) during next E+exp
#pragma unroll
            for (int k = 0; k < 4; ++k) {
                int idx8 = tid + k * 512;
                int c = idx8 >> 4, j = (idx8 & 15) << 3;
                cpa16(vs_u + (c * 136 + j) * 2,
                      &g_v[((size_t)b * CC + c) * NN + nb + 128 + j]);
            }
            CPA_COMMIT();
        }
    }

    // ---------------- epilogue ----------------
#pragma unroll
    for (int i = 0; i < 8; ++i) {
        float v = csum[i];
        v += __shfl_xor_sync(0xffffffffu, v, 4);
        v += __shfl_xor_sync(0xffffffffu, v, 8);
        v += __shfl_xor_sync(0xffffffffu, v, 16);
        if (qr == 0) atomicAdd(&csum_s[col0 + (i >> 1) * 8 + 2 * ql + (i & 1)], v);
    }
    __syncthreads();
    if (tid < 128) cinv_s[tid] = 1.0f / (1e-9f + csum_s[tid]);
    __syncthreads();

    // xmT[m][c] = x - Y*cinv  (fp32 overlay, stride 132)
    const float* xb = x + ((size_t)b * CC) * NN + m0;
#pragma unroll
    for (int mi = 0; mi < 2; ++mi) {
        int r = row0 + mi * 16 + qr;
#pragma unroll
        for (int ni = 0; ni < 4; ++ni) {
            int col = col0 + ni * 8 + 2 * ql;
            float2 x0 = __ldg((const float2*)&xb[(size_t)r * NN + col]);
            float2 x1 = __ldg((const float2*)&xb[(size_t)(r + 8) * NN + col]);
            float ci0 = cinv_s[col], ci1 = cinv_s[col + 1];
            xmT[col * 132 + r]           = to_tf32(x0.x - yacc[mi][ni][0] * ci0);
            xmT[(col + 1) * 132 + r]     = to_tf32(x0.y - yacc[mi][ni][1] * ci1);
            xmT[col * 132 + r + 8]       = to_tf32(x1.x - yacc[mi][ni][2] * ci0);
            xmT[(col + 1) * 132 + r + 8] = to_tf32(x1.y - yacc[mi][ni][3] * ci1);
        }
    }
    __syncthreads();

    // t = wt @ xm  (tf32; wt fragments from gmem, L2/L1-resident)
    float tacc[2][4][4] = {};
#pragma unroll
    for (int ks = 0; ks < 16; ++ks) {
        const int k0 = ks * 8;
        uint32_t A[2][4];
#pragma unroll
        for (int mi = 0; mi < 2; ++mi) {
            int r = row0 + mi * 16 + qr;
            A[mi][0] = fu(to_tf32(__ldg(&wt[r * CC + k0 + ql])));
            A[mi][1] = fu(to_tf32(__ldg(&wt[(r + 8) * CC + k0 + ql])));
            A[mi][2] = fu(to_tf32(__ldg(&wt[r * CC + k0 + 4 + ql])));
            A[mi][3] = fu(to_tf32(__ldg(&wt[(r + 8) * CC + k0 + 4 + ql])));
        }
#pragma unroll
        for (int ni = 0; ni < 4; ++ni) {
            int cb = col0 + ni * 8 + qr;
            uint32_t b0 = fu(xmT[cb * 132 + k0 + ql]);
            uint32_t b1 = fu(xmT[cb * 132 + k0 + 4 + ql]);
            mma8(tacc[0][ni], A[0][0], A[0][1], A[0][2], A[0][3], b0, b1);
            mma8(tacc[1][ni], A[1][0], A[1][1], A[1][2], A[1][3], b0, b1);
        }
    }

    // out = x + relu(t*A + S)
#pragma unroll
    for (int mi = 0; mi < 2; ++mi) {
        int r = row0 + mi * 16 + qr;
        float a0 = A_s[r], s0 = S_s[r];
        float a1 = A_s[r + 8], s1 = S_s[r + 8];
#pragma unroll
        for (int ni = 0; ni < 4; ++ni) {
            int col = col0 + ni * 8 + 2 * ql;
            float2 x0 = __ldg((const float2*)&xb[(size_t)r * NN + col]);
            float2 x1 = __ldg((const float2*)&xb[(size_t)(r + 8) * NN + col]);
            float2 o0, o1;
            o0.x = x0.x + fmaxf(fmaf(tacc[mi][ni][0], a0, s0), 0.f);
            o0.y = x0.y + fmaxf(fmaf(tacc[mi][ni][1], a0, s0), 0.f);
            o1.x = x1.x + fmaxf(fmaf(tacc[mi][ni][2], a1, s1), 0.f);
            o1.y = x1.y + fmaxf(fmaf(tacc[mi][ni][3], a1, s1), 0.f);
            *(float2*)&out[((size_t)b * CC + r) * NN + m0 + col]     = o0;
            *(float2*)&out[((size_t)b * CC + r + 8) * NN + m0 + col] = o1;
        }
    }
}

// ======================================================================
extern "C" void kernel_launch(void* const* d_in, const int* in_sizes, int n_in,
                              void* d_out, int out_size) {
    const float* x     = (const float*)d_in[0];
    const float* wq    = (const float*)d_in[1];
    const float* wv    = (const float*)d_in[2];
    const float* bv    = (const float*)d_in[3];
    const float* wt    = (const float*)d_in[4];
    const float* bt    = (const float*)d_in[5];
    const float* gamma = (const float*)d_in[6];
    const float* beta  = (const float*)d_in[7];
    const float* mean  = (const float*)d_in[8];
    const float* var   = (const float*)d_in[9];
    float* out = (float*)d_out;

    const int S1 = (16896 + 21120 + 4128 + 128) * 4;   // 169088
    const int S2 = (128 + 3 * 4608) * 4;               // 55808
    const int S3 = 109056;

    cudaFuncSetAttribute(k_qv,     cudaFuncAttributeMaxDynamicSharedMemorySize, S1);
    cudaFuncSetAttribute(k_rowsum, cudaFuncAttributeMaxDynamicSharedMemorySize, S2);
    cudaFuncSetAttribute(k_attn,   cudaFuncAttributeMaxDynamicSharedMemorySize, S3);

    k_qv<<<dim3(16, 16), 640, S1>>>(x, wq, wv, bv);
    k_rowsum<<<dim3(16, 16), 512, S2>>>();
    k_attn<<<dim3(16, 16), 512, S3>>>(x, wt, bt, gamma, beta, mean, var, out);
}

// round 7
// speedup vs baseline: 1.5031x; 1.0938x over previous
#include <cuda_runtime.h>
#include <cuda_fp16.h>
#include <cstdint>

#define BB 16
#define CC 128
#define DD 32
#define NN 2048
#define SQRT_LOG2E 1.2011224087864498f

// ---------------- device scratch (static) ----------------
__device__ float  g_qs[BB * NN * DD];   // qT[b][n][d], *sqrt(log2e), tf32-rounded
__device__ __half g_qh[BB * NN * DD];   // same, fp16 (for rowsum kernel)
__device__ __half g_v [BB * CC * NN];   // v[b][c][n], fp16
__device__ float  g_rl[BB * NN];        // log2(rowsum)

// ---------------- helpers ----------------
__device__ __forceinline__ float to_tf32(float x) {
    uint32_t u; asm("cvt.rna.tf32.f32 %0, %1;" : "=r"(u) : "f"(x));
    return __uint_as_float(u);
}
__device__ __forceinline__ float ex2f(float x) {
    float y; asm("ex2.approx.ftz.f32 %0, %1;" : "=f"(y) : "f"(x)); return y;
}
__device__ __forceinline__ float lg2f(float x) {
    float y; asm("lg2.approx.f32 %0, %1;" : "=f"(y) : "f"(x)); return y;
}
__device__ __forceinline__ void mma8(float c[4],
                                     uint32_t a0, uint32_t a1, uint32_t a2, uint32_t a3,
                                     uint32_t b0, uint32_t b1) {
    asm volatile(
        "mma.sync.aligned.m16n8k8.row.col.f32.tf32.tf32.f32 "
        "{%0,%1,%2,%3}, {%4,%5,%6,%7}, {%8,%9}, {%0,%1,%2,%3};"
        : "+f"(c[0]), "+f"(c[1]), "+f"(c[2]), "+f"(c[3])
        : "r"(a0), "r"(a1), "r"(a2), "r"(a3), "r"(b0), "r"(b1));
}
__device__ __forceinline__ void mma16h(float c[4],
                                       uint32_t a0, uint32_t a1, uint32_t a2, uint32_t a3,
                                       uint32_t b0, uint32_t b1) {
    asm volatile(
        "mma.sync.aligned.m16n8k16.row.col.f32.f16.f16.f32 "
        "{%0,%1,%2,%3}, {%4,%5,%6,%7}, {%8,%9}, {%0,%1,%2,%3};"
        : "+f"(c[0]), "+f"(c[1]), "+f"(c[2]), "+f"(c[3])
        : "r"(a0), "r"(a1), "r"(a2), "r"(a3), "r"(b0), "r"(b1));
}
__device__ __forceinline__ void ldsm4(uint32_t r[4], uint32_t addr) {
    asm volatile("ldmatrix.sync.aligned.m8n8.x4.shared.b16 {%0,%1,%2,%3}, [%4];"
        : "=r"(r[0]), "=r"(r[1]), "=r"(r[2]), "=r"(r[3]) : "r"(addr));
}
__device__ __forceinline__ void ldsm4t(uint32_t r[4], uint32_t addr) {
    asm volatile("ldmatrix.sync.aligned.m8n8.x4.trans.shared.b16 {%0,%1,%2,%3}, [%4];"
        : "=r"(r[0]), "=r"(r[1]), "=r"(r[2]), "=r"(r[3]) : "r"(addr));
}
__device__ __forceinline__ uint32_t fu(float f) { return __float_as_uint(f); }
__device__ __forceinline__ uint32_t smem_u32(const void* p) {
    uint32_t a;
    asm("{ .reg .u64 t; cvta.to.shared.u64 t, %1; cvt.u32.u64 %0, t; }" : "=r"(a) : "l"(p));
    return a;
}
__device__ __forceinline__ void cpa16(uint32_t dst, const void* src) {
    asm volatile("cp.async.cg.shared.global [%0], [%1], 16;" :: "r"(dst), "l"(src));
}
#define CPA_COMMIT() asm volatile("cp.async.commit_group;" ::: "memory")
#define CPA_WAIT(n)  asm volatile("cp.async.wait_group %0;" :: "n"(n) : "memory")

// ======================================================================
// k1: q = wq@x (scaled, tf32 + fp16) ; v = wv@x + bv (fp16)
// 640 threads (20 warps, 32x32 warp tiles on a 160x128 output).
// ======================================================================
__global__ __launch_bounds__(640) void k_qv(const float* __restrict__ x,
                                            const float* __restrict__ wq,
                                            const float* __restrict__ wv,
                                            const float* __restrict__ bv) {
    extern __shared__ float sm[];
    float* xT   = sm;             // 128*132  xT[n][c]
    float* ws   = sm + 16896;     // 160*132  ws[r][c]
    float* qb   = sm + 38016;     // 32*129
    float* bv_s = sm + 42144;     // 128
    const int b  = blockIdx.y;
    const int n0 = blockIdx.x * 128;
    const int tid = threadIdx.x;
    const float* xb = x + (size_t)b * CC * NN;

    for (int i = tid; i < CC * 128; i += 640) {
        int c = i >> 7, n = i & 127;
        xT[n * 132 + c] = xb[(size_t)c * NN + n0 + n];
    }
    for (int i = tid; i < 160 * 128; i += 640) {
        int r = i >> 7, c = i & 127;
        ws[r * 132 + c] = (r < DD) ? wq[r * CC + c] : wv[(r - DD) * CC + c];
    }
    if (tid < CC) bv_s[tid] = bv[tid];
    __syncthreads();

    const int w = tid >> 5, lane = tid & 31;
    const int rg = w >> 2, cg = w & 3;
    const int row0 = rg * 32, col0 = cg * 32;
    const int qr = lane >> 2, ql = lane & 3;

    float acc[2][4][4] = {};
#pragma unroll
    for (int ks = 0; ks < 16; ++ks) {
        const int k0 = ks * 8;
        uint32_t A[2][4];
#pragma unroll
        for (int mi = 0; mi < 2; ++mi) {
            int r = row0 + mi * 16 + qr;
            A[mi][0] = fu(ws[r * 132 + k0 + ql]);
            A[mi][1] = fu(ws[(r + 8) * 132 + k0 + ql]);
            A[mi][2] = fu(ws[r * 132 + k0 + 4 + ql]);
            A[mi][3] = fu(ws[(r + 8) * 132 + k0 + 4 + ql]);
        }
#pragma unroll
        for (int ni = 0; ni < 4; ++ni) {
            int cb = col0 + ni * 8 + qr;
            uint32_t b0 = fu(xT[cb * 132 + k0 + ql]);
            uint32_t b1 = fu(xT[cb * 132 + k0 + 4 + ql]);
            mma8(acc[0][ni], A[0][0], A[0][1], A[0][2], A[0][3], b0, b1);
            mma8(acc[1][ni], A[1][0], A[1][1], A[1][2], A[1][3], b0, b1);
        }
    }

    if (rg == 0) {
#pragma unroll
        for (int mi = 0; mi < 2; ++mi) {
            int d = mi * 16 + qr;
#pragma unroll
            for (int ni = 0; ni < 4; ++ni) {
                int col = col0 + ni * 8 + 2 * ql;
                qb[d * 129 + col]           = to_tf32(acc[mi][ni][0] * SQRT_LOG2E);
                qb[d * 129 + col + 1]       = to_tf32(acc[mi][ni][1] * SQRT_LOG2E);
                qb[(d + 8) * 129 + col]     = to_tf32(acc[mi][ni][2] * SQRT_LOG2E);
                qb[(d + 8) * 129 + col + 1] = to_tf32(acc[mi][ni][3] * SQRT_LOG2E);
            }
        }
    } else {
#pragma unroll
        for (int mi = 0; mi < 2; ++mi) {
            int rv = row0 - DD + mi * 16 + qr;
            float b0v = bv_s[rv], b1v = bv_s[rv + 8];
#pragma unroll
            for (int ni = 0; ni < 4; ++ni) {
                int col = col0 + ni * 8 + 2 * ql;
                *(half2*)&g_v[((size_t)b * CC + rv) * NN + n0 + col] =
                    __floats2half2_rn(acc[mi][ni][0] + b0v, acc[mi][ni][1] + b0v);
                *(half2*)&g_v[((size_t)b * CC + rv + 8) * NN + n0 + col] =
                    __floats2half2_rn(acc[mi][ni][2] + b1v, acc[mi][ni][3] + b1v);
            }
        }
    }
    __syncthreads();
    for (int i = tid; i < 128 * DD; i += 640) {
        int n = i >> 5, d = i & 31;
        g_qs[((size_t)b * NN + n0 + n) * DD + d] = qb[d * 129 + n];
    }
    for (int i = tid; i < 128 * 16; i += 640) {
        int n = i >> 4, d2 = (i & 15) << 1;
        *(half2*)&g_qh[((size_t)b * NN + n0 + n) * DD + d2] =
            __floats2half2_rn(qb[d2 * 129 + n], qb[(d2 + 1) * 129 + n]);
    }
}

// ======================================================================
// k2: rl[n] = log2( sum_m exp2(E[n,m]) ), E via fp16 mma + ldmatrix.
// 512 threads, 2 CTAs/SM, double-buffered qm via cp.async.
// smem: red[128]f, qn_h 128x40 h, qm0/qm1 128x40 h
// ======================================================================
__global__ __launch_bounds__(512, 2) void k_rowsum() {
    extern __shared__ float sm[];
    float*  red  = sm;                          // 128 f
    __half* qn_h = (__half*)(sm + 128);         // stride 40
    __half* qm0  = qn_h + 128 * 40;
    __half* qm1  = qm0 + 128 * 40;

    const int tid = threadIdx.x, w = tid >> 5, lane = tid & 31;
    const int row0 = (w & 3) * 32, col0 = (w >> 2) * 32;
    const int b = blockIdx.y, n0 = blockIdx.x * 128;
    const uint32_t qn_u = smem_u32(qn_h), qm0u = smem_u32(qm0), qm1u = smem_u32(qm1);
    // ldmatrix lane offsets
    const int la = ((lane >> 3) & 1) * 8 + (lane & 7);   // A: row offset
    const int lc = (lane >> 4) * 8;                      // A: col offset
    const int lbr = (lane >> 4) * 8 + (lane & 7);        // B: row offset
    const int lbc = ((lane >> 3) & 1) * 8;               // B: col offset

    if (tid < 128) red[tid] = 0.f;
    {   // stage qn (fp16, 16B = 8 halves per chunk; 512 chunks)
        int r = tid >> 2, j = (tid & 3) << 3;
        cpa16(qn_u + (r * 40 + j) * 2, &g_qh[((size_t)b * NN + n0 + r) * DD + j]);
    }
    CPA_COMMIT();
    {   // prefetch qm(0)
        int r = tid >> 2, j = (tid & 3) << 3;
        cpa16(qm0u + (r * 40 + j) * 2, &g_qh[((size_t)b * NN + r) * DD + j]);
    }
    CPA_COMMIT();

    float racc[2][2] = {};
    for (int mt = 0; mt < NN / 128; ++mt) {
        const uint32_t qmu = (mt & 1) ? qm1u : qm0u;
        const uint32_t qmnu = (mt & 1) ? qm0u : qm1u;
        CPA_WAIT(0);
        __syncthreads();
        if (mt + 1 < NN / 128) {
            int r = tid >> 2, j = (tid & 3) << 3;
            cpa16(qmnu + (r * 40 + j) * 2,
                  &g_qh[((size_t)b * NN + (mt + 1) * 128 + r) * DD + j]);
            CPA_COMMIT();
        }

        float e[2][4][4] = {};
#pragma unroll
        for (int ks = 0; ks < 2; ++ks) {
            const int k0 = ks * 16;
            uint32_t A[2][4], Bp[2][4];
#pragma unroll
            for (int mi = 0; mi < 2; ++mi)
                ldsm4(A[mi], qn_u + ((row0 + mi * 16 + la) * 40 + k0 + lc) * 2);
#pragma unroll
            for (int p = 0; p < 2; ++p)
                ldsm4(Bp[p], qmu + ((col0 + p * 16 + lbr) * 40 + k0 + lbc) * 2);
#pragma unroll
            for (int mi = 0; mi < 2; ++mi)
#pragma unroll
                for (int ni = 0; ni < 4; ++ni)
                    mma16h(e[mi][ni], A[mi][0], A[mi][1], A[mi][2], A[mi][3],
                           Bp[ni >> 1][(ni & 1) * 2], Bp[ni >> 1][(ni & 1) * 2 + 1]);
        }
#pragma unroll
        for (int mi = 0; mi < 2; ++mi)
#pragma unroll
            for (int ni = 0; ni < 4; ++ni) {
                racc[mi][0] += ex2f(e[mi][ni][0]) + ex2f(e[mi][ni][1]);
                racc[mi][1] += ex2f(e[mi][ni][2]) + ex2f(e[mi][ni][3]);
            }
    }

    const int qr = lane >> 2, ql = lane & 3;
#pragma unroll
    for (int mi = 0; mi < 2; ++mi)
#pragma unroll
        for (int h = 0; h < 2; ++h) {
            float v = racc[mi][h];
            v += __shfl_xor_sync(0xffffffffu, v, 1);
            v += __shfl_xor_sync(0xffffffffu, v, 2);
            racc[mi][h] = v;
        }
    if (ql == 0) {
        atomicAdd(&red[row0 + qr],          racc[0][0]);
        atomicAdd(&red[row0 + qr + 8],      racc[0][1]);
        atomicAdd(&red[row0 + 16 + qr],     racc[1][0]);
        atomicAdd(&red[row0 + 16 + qr + 8], racc[1][1]);
    }
    __syncthreads();
    if (tid < 128) g_rl[(size_t)b * NN + n0 + tid] = lg2f(red[tid]);
}

// ======================================================================
// k3: fused attention + epilogue. 512 threads, 128x128 tiles.
// E tf32; p = exp2(e - rl) stored [n][m] fp16 (coalesced half2);
// Y fp16 via ldmatrix(.trans); epilogue t = wt@xm tf32.
// smem: header 640 f; qm_s/qn_s 128x36 f; vs_h/pn_h 128x136 h;
//       xmT fp32 128x132 overlays vs_h/pn_h region. total 109056 B.
// ======================================================================
__global__ __launch_bounds__(512, 1) void k_attn(const float* __restrict__ x,
                                                 const float* __restrict__ wt,
                                                 const float* __restrict__ bt,
                                                 const float* __restrict__ gamma,
                                                 const float* __restrict__ beta,
                                                 const float* __restrict__ mean,
                                                 const float* __restrict__ var,
                                                 float* __restrict__ out) {
    extern __shared__ float sm[];
    char* smc = (char*)sm;
    float* csum_s = sm;             // 128
    float* cinv_s = sm + 128;
    float* A_s    = sm + 256;
    float* S_s    = sm + 384;
    float* rl_s   = sm + 512;
    float* qm_s   = sm + 640;       // stride 36
    float* qn_s   = sm + 5248;      // stride 36
    __half* vs_h  = (__half*)(smc + 39424);   // [c][n] stride 136
    __half* pn_h  = (__half*)(smc + 74240);   // [n][m] stride 136
    float*  xmT   = (float*)(smc + 39424);    // epilogue overlay, stride 132

    const int tid = threadIdx.x, w = tid >> 5, lane = tid & 31;
    const int row0 = (w & 3) * 32, col0 = (w >> 2) * 32;
    const int qr = lane >> 2, ql = lane & 3;
    const int b = blockIdx.y, m0 = blockIdx.x * 128;
    const uint32_t qn_u = smem_u32(qn_s), vs_u = smem_u32(vs_h), pn_u = smem_u32(pn_h);
    const int la = ((lane >> 3) & 1) * 8 + (lane & 7);
    const int lc = (lane >> 4) * 8;

    if (tid < 128) {
        csum_s[tid] = 0.f;
        float A = gamma[tid] * rsqrtf(var[tid] + 1e-5f);
        A_s[tid] = A;
        S_s[tid] = beta[tid] + (bt[tid] - mean[tid]) * A;
    }
    for (int i = tid; i < 128 * DD; i += 512) {
        int r = i >> 5, d = i & 31;
        qm_s[r * 36 + d] = g_qs[((size_t)b * NN + m0 + r) * DD + d];
    }
    // prologue prefetch: qn(0), vs(0)
#pragma unroll
    for (int k = 0; k < 2; ++k) {
        int idx4 = tid + k * 512;
        int r = idx4 >> 3, d4 = (idx4 & 7) << 2;
        cpa16(qn_u + (r * 36 + d4) * 4, &g_qs[((size_t)b * NN + r) * DD + d4]);
    }
    CPA_COMMIT();
#pragma unroll
    for (int k = 0; k < 4; ++k) {
        int idx8 = tid + k * 512;
        int c = idx8 >> 4, j = (idx8 & 15) << 3;
        cpa16(vs_u + (c * 136 + j) * 2, &g_v[((size_t)b * CC + c) * NN + j]);
    }
    CPA_COMMIT();

    float yacc[2][4][4] = {};
    float csum[8] = {};

    for (int nt = 0; nt < NN / 128; ++nt) {
        const int nb = nt * 128;
        if (tid < 128) rl_s[tid] = g_rl[(size_t)b * NN + nb + tid];
        CPA_WAIT(1);                 // qn(nt) ready
        __syncthreads();

        // ---- E = qn . qm^T (tf32) ----
        float e[2][4][4] = {};
#pragma unroll
        for (int ks = 0; ks < 4; ++ks) {
            const int k0 = ks * 8;
            uint32_t A[2][4];
#pragma unroll
            for (int mi = 0; mi < 2; ++mi) {
                int r = row0 + mi * 16 + qr;
                A[mi][0] = fu(qn_s[r * 36 + k0 + ql]);
                A[mi][1] = fu(qn_s[(r + 8) * 36 + k0 + ql]);
                A[mi][2] = fu(qn_s[r * 36 + k0 + 4 + ql]);
                A[mi][3] = fu(qn_s[(r + 8) * 36 + k0 + 4 + ql]);
            }
#pragma unroll
            for (int ni = 0; ni < 4; ++ni) {
                int cb = col0 + ni * 8 + qr;
                uint32_t b0 = fu(qm_s[cb * 36 + k0 + ql]);
                uint32_t b1 = fu(qm_s[cb * 36 + k0 + 4 + ql]);
                mma8(e[0][ni], A[0][0], A[0][1], A[0][2], A[0][3], b0, b1);
                mma8(e[1][ni], A[1][0], A[1][1], A[1][2], A[1][3], b0, b1);
            }
        }

        // ---- p = exp2(e - rl[n]); csum; store [n][m] fp16 half2 ----
#pragma unroll
        for (int mi = 0; mi < 2; ++mi) {
            int r = row0 + mi * 16 + qr;
            float rl0 = rl_s[r], rl1 = rl_s[r + 8];
#pragma unroll
            for (int ni = 0; ni < 4; ++ni) {
                int col = col0 + ni * 8 + 2 * ql;
                float p00 = ex2f(e[mi][ni][0] - rl0);
                float p01 = ex2f(e[mi][ni][1] - rl0);
                float p10 = ex2f(e[mi][ni][2] - rl1);
                float p11 = ex2f(e[mi][ni][3] - rl1);
                csum[ni * 2]     += p00 + p10;
                csum[ni * 2 + 1] += p01 + p11;
                *(half2*)&pn_h[r * 136 + col]       = __floats2half2_rn(p00, p01);
                *(half2*)&pn_h[(r + 8) * 136 + col] = __floats2half2_rn(p10, p11);
            }
        }
        CPA_WAIT(0);                 // vs(nt) ready
        __syncthreads();             // pn visible; qn reads done

        if (nt + 1 < NN / 128) {     // prefetch qn(nt+1) during Y-mma
#pragma unroll
            for (int k = 0; k < 2; ++k) {
                int idx4 = tid + k * 512;
                int r = idx4 >> 3, d4 = (idx4 & 7) << 2;
                cpa16(qn_u + (r * 36 + d4) * 4,
                      &g_qs[((size_t)b * NN + nb + 128 + r) * DD + d4]);
            }
            CPA_COMMIT();
        }

        // ---- Y += v @ p (fp16, ldmatrix) ----
#pragma unroll
        for (int ks = 0; ks < 8; ++ks) {
            const int k0 = ks * 16;
            uint32_t A[2][4], Bp[2][4];
#pragma unroll
            for (int mi = 0; mi < 2; ++mi)
                ldsm4(A[mi], vs_u + ((row0 + mi * 16 + la) * 136 + k0 + lc) * 2);
#pragma unroll
            for (int p = 0; p < 2; ++p)
                ldsm4t(Bp[p], pn_u + ((k0 + la) * 136 + col0 + p * 16 + lc) * 2);
#pragma unroll
            for (int mi = 0; mi < 2; ++mi)
#pragma unroll
                for (int ni = 0; ni < 4; ++ni)
                    mma16h(yacc[mi][ni], A[mi][0], A[mi][1], A[mi][2], A[mi][3],
                           Bp[ni >> 1][(ni & 1) * 2], Bp[ni >> 1][(ni & 1) * 2 + 1]);
        }
        __syncthreads();             // vs/pn reads done
        if (nt + 1 < NN / 128) {     // prefetch vs(nt+1) during next E+exp
#pragma unroll
            for (int k = 0; k < 4; ++k) {
                int idx8 = tid + k * 512;
                int c = idx8 >> 4, j = (idx8 & 15) << 3;
                cpa16(vs_u + (c * 136 + j) * 2,
                      &g_v[((size_t)b * CC + c) * NN + nb + 128 + j]);
            }
            CPA_COMMIT();
        }
    }

    // ---------------- epilogue ----------------
#pragma unroll
    for (int i = 0; i < 8; ++i) {
        float v = csum[i];
        v += __shfl_xor_sync(0xffffffffu, v, 4);
        v += __shfl_xor_sync(0xffffffffu, v, 8);
        v += __shfl_xor_sync(0xffffffffu, v, 16);
        if (qr == 0) atomicAdd(&csum_s[col0 + (i >> 1) * 8 + 2 * ql + (i & 1)], v);
    }
    __syncthreads();
    if (tid < 128) cinv_s[tid] = 1.0f / (1e-9f + csum_s[tid]);
    __syncthreads();

    // xmT[m][c] = x - Y*cinv  (fp32 overlay, stride 132)
    const float* xb = x + ((size_t)b * CC) * NN + m0;
#pragma unroll
    for (int mi = 0; mi < 2; ++mi) {
        int r = row0 + mi * 16 + qr;
#pragma unroll
        for (int ni = 0; ni < 4; ++ni) {
            int col = col0 + ni * 8 + 2 * ql;
            float2 x0 = __ldg((const float2*)&xb[(size_t)r * NN + col]);
            float2 x1 = __ldg((const float2*)&xb[(size_t)(r + 8) * NN + col]);
            float ci0 = cinv_s[col], ci1 = cinv_s[col + 1];
            xmT[col * 132 + r]           = to_tf32(x0.x - yacc[mi][ni][0] * ci0);
            xmT[(col + 1) * 132 + r]     = to_tf32(x0.y - yacc[mi][ni][1] * ci1);
            xmT[col * 132 + r + 8]       = to_tf32(x1.x - yacc[mi][ni][2] * ci0);
            xmT[(col + 1) * 132 + r + 8] = to_tf32(x1.y - yacc[mi][ni][3] * ci1);
        }
    }
    __syncthreads();

    // t = wt @ xm  (tf32; wt fragments from gmem, L2-resident)
    float tacc[2][4][4] = {};
#pragma unroll
    for (int ks = 0; ks < 16; ++ks) {
        const int k0 = ks * 8;
        uint32_t A[2][4];
#pragma unroll
        for (int mi = 0; mi < 2; ++mi) {
            int r = row0 + mi * 16 + qr;
            A[mi][0] = fu(to_tf32(__ldg(&wt[r * CC + k0 + ql])));
            A[mi][1] = fu(to_tf32(__ldg(&wt[(r + 8) * CC + k0 + ql])));
            A[mi][2] = fu(to_tf32(__ldg(&wt[r * CC + k0 + 4 + ql])));
            A[mi][3] = fu(to_tf32(__ldg(&wt[(r + 8) * CC + k0 + 4 + ql])));
        }
#pragma unroll
        for (int ni = 0; ni < 4; ++ni) {
            int cb = col0 + ni * 8 + qr;
            uint32_t b0 = fu(xmT[cb * 132 + k0 + ql]);
            uint32_t b1 = fu(xmT[cb * 132 + k0 + 4 + ql]);
            mma8(tacc[0][ni], A[0][0], A[0][1], A[0][2], A[0][3], b0, b1);
            mma8(tacc[1][ni], A[1][0], A[1][1], A[1][2], A[1][3], b0, b1);
        }
    }

    // out = x + relu(t*A + S)
#pragma unroll
    for (int mi = 0; mi < 2; ++mi) {
        int r = row0 + mi * 16 + qr;
        float a0 = A_s[r], s0 = S_s[r];
        float a1 = A_s[r + 8], s1 = S_s[r + 8];
#pragma unroll
        for (int ni = 0; ni < 4; ++ni) {
            int col = col0 + ni * 8 + 2 * ql;
            float2 x0 = __ldg((const float2*)&xb[(size_t)r * NN + col]);
            float2 x1 = __ldg((const float2*)&xb[(size_t)(r + 8) * NN + col]);
            float2 o0, o1;
            o0.x = x0.x + fmaxf(fmaf(tacc[mi][ni][0], a0, s0), 0.f);
            o0.y = x0.y + fmaxf(fmaf(tacc[mi][ni][1], a0, s0), 0.f);
            o1.x = x1.x + fmaxf(fmaf(tacc[mi][ni][2], a1, s1), 0.f);
            o1.y = x1.y + fmaxf(fmaf(tacc[mi][ni][3], a1, s1), 0.f);
            *(float2*)&out[((size_t)b * CC + r) * NN + m0 + col]     = o0;
            *(float2*)&out[((size_t)b * CC + r + 8) * NN + m0 + col] = o1;
        }
    }
}

// ======================================================================
extern "C" void kernel_launch(void* const* d_in, const int* in_sizes, int n_in,
                              void* d_out, int out_size) {
    const float* x     = (const float*)d_in[0];
    const float* wq    = (const float*)d_in[1];
    const float* wv    = (const float*)d_in[2];
    const float* bv    = (const float*)d_in[3];
    const float* wt    = (const float*)d_in[4];
    const float* bt    = (const float*)d_in[5];
    const float* gamma = (const float*)d_in[6];
    const float* beta  = (const float*)d_in[7];
    const float* mean  = (const float*)d_in[8];
    const float* var   = (const float*)d_in[9];
    float* out = (float*)d_out;

    const int S1 = (16896 + 21120 + 4128 + 128) * 4;   // 169088
    const int S2 = 128 * 4 + 3 * 128 * 40 * 2;         // 31232
    const int S3 = 109056;

    cudaFuncSetAttribute(k_qv,     cudaFuncAttributeMaxDynamicSharedMemorySize, S1);
    cudaFuncSetAttribute(k_rowsum, cudaFuncAttributeMaxDynamicSharedMemorySize, S2);
    cudaFuncSetAttribute(k_attn,   cudaFuncAttributeMaxDynamicSharedMemorySize, S3);

    k_qv<<<dim3(16, 16), 640, S1>>>(x, wq, wv, bv);
    k_rowsum<<<dim3(16, 16), 512, S2>>>();
    k_attn<<<dim3(16, 16), 512, S3>>>(x, wt, bt, gamma, beta, mean, var, out);
}

// round 8
// speedup vs baseline: 1.6764x; 1.1153x over previous
#include <cuda_runtime.h>
#include <cuda_fp16.h>
#include <cstdint>

#define BB 16
#define CC 128
#define DD 32
#define NN 2048
#define SQRT_LOG2E 1.2011224087864498f

// ---------------- device scratch (static) ----------------
__device__ __half g_qh[BB * NN * DD];   // qT[b][n][d], *sqrt(log2e), fp16
__device__ __half g_v [BB * CC * NN];   // v[b][c][n], fp16
__device__ float  g_rl[BB * NN];        // log2(rowsum)

// ---------------- helpers ----------------
__device__ __forceinline__ float to_tf32(float x) {
    uint32_t u; asm("cvt.rna.tf32.f32 %0, %1;" : "=r"(u) : "f"(x));
    return __uint_as_float(u);
}
__device__ __forceinline__ float ex2f(float x) {
    float y; asm("ex2.approx.ftz.f32 %0, %1;" : "=f"(y) : "f"(x)); return y;
}
__device__ __forceinline__ float lg2f(float x) {
    float y; asm("lg2.approx.f32 %0, %1;" : "=f"(y) : "f"(x)); return y;
}
__device__ __forceinline__ void mma8(float c[4],
                                     uint32_t a0, uint32_t a1, uint32_t a2, uint32_t a3,
                                     uint32_t b0, uint32_t b1) {
    asm volatile(
        "mma.sync.aligned.m16n8k8.row.col.f32.tf32.tf32.f32 "
        "{%0,%1,%2,%3}, {%4,%5,%6,%7}, {%8,%9}, {%0,%1,%2,%3};"
        : "+f"(c[0]), "+f"(c[1]), "+f"(c[2]), "+f"(c[3])
        : "r"(a0), "r"(a1), "r"(a2), "r"(a3), "r"(b0), "r"(b1));
}
__device__ __forceinline__ void mma16h(float c[4],
                                       uint32_t a0, uint32_t a1, uint32_t a2, uint32_t a3,
                                       uint32_t b0, uint32_t b1) {
    asm volatile(
        "mma.sync.aligned.m16n8k16.row.col.f32.f16.f16.f32 "
        "{%0,%1,%2,%3}, {%4,%5,%6,%7}, {%8,%9}, {%0,%1,%2,%3};"
        : "+f"(c[0]), "+f"(c[1]), "+f"(c[2]), "+f"(c[3])
        : "r"(a0), "r"(a1), "r"(a2), "r"(a3), "r"(b0), "r"(b1));
}
__device__ __forceinline__ void ldsm4(uint32_t r[4], uint32_t addr) {
    asm volatile("ldmatrix.sync.aligned.m8n8.x4.shared.b16 {%0,%1,%2,%3}, [%4];"
        : "=r"(r[0]), "=r"(r[1]), "=r"(r[2]), "=r"(r[3]) : "r"(addr));
}
__device__ __forceinline__ void ldsm4t(uint32_t r[4], uint32_t addr) {
    asm volatile("ldmatrix.sync.aligned.m8n8.x4.trans.shared.b16 {%0,%1,%2,%3}, [%4];"
        : "=r"(r[0]), "=r"(r[1]), "=r"(r[2]), "=r"(r[3]) : "r"(addr));
}
__device__ __forceinline__ uint32_t fu(float f) { return __float_as_uint(f); }
__device__ __forceinline__ uint32_t smem_u32(const void* p) {
    uint32_t a;
    asm("{ .reg .u64 t; cvta.to.shared.u64 t, %1; cvt.u32.u64 %0, t; }" : "=r"(a) : "l"(p));
    return a;
}
__device__ __forceinline__ void cpa16(uint32_t dst, const void* src) {
    asm volatile("cp.async.cg.shared.global [%0], [%1], 16;" :: "r"(dst), "l"(src));
}
#define CPA_COMMIT() asm volatile("cp.async.commit_group;" ::: "memory")
#define CPA_WAIT(n)  asm volatile("cp.async.wait_group %0;" :: "n"(n) : "memory")

// ======================================================================
// k1: q = wq@x (scaled, fp16) ; v = wv@x + bv (fp16)  — tf32 compute
// 640 threads (20 warps, 32x32 warp tiles on a 160x128 output).
// ======================================================================
__global__ __launch_bounds__(640) void k_qv(const float* __restrict__ x,
                                            const float* __restrict__ wq,
                                            const float* __restrict__ wv,
                                            const float* __restrict__ bv) {
    extern __shared__ float sm[];
    float* xT   = sm;             // 128*132  xT[n][c]
    float* ws   = sm + 16896;     // 160*132  ws[r][c]
    float* qb   = sm + 38016;     // 32*129
    float* bv_s = sm + 42144;     // 128
    const int b  = blockIdx.y;
    const int n0 = blockIdx.x * 128;
    const int tid = threadIdx.x;
    const float* xb = x + (size_t)b * CC * NN;

    for (int i = tid; i < CC * 128; i += 640) {
        int c = i >> 7, n = i & 127;
        xT[n * 132 + c] = xb[(size_t)c * NN + n0 + n];
    }
    for (int i = tid; i < 160 * 128; i += 640) {
        int r = i >> 7, c = i & 127;
        ws[r * 132 + c] = (r < DD) ? wq[r * CC + c] : wv[(r - DD) * CC + c];
    }
    if (tid < CC) bv_s[tid] = bv[tid];
    __syncthreads();

    const int w = tid >> 5, lane = tid & 31;
    const int rg = w >> 2, cg = w & 3;
    const int row0 = rg * 32, col0 = cg * 32;
    const int qr = lane >> 2, ql = lane & 3;

    float acc[2][4][4] = {};
#pragma unroll
    for (int ks = 0; ks < 16; ++ks) {
        const int k0 = ks * 8;
        uint32_t A[2][4];
#pragma unroll
        for (int mi = 0; mi < 2; ++mi) {
            int r = row0 + mi * 16 + qr;
            A[mi][0] = fu(ws[r * 132 + k0 + ql]);
            A[mi][1] = fu(ws[(r + 8) * 132 + k0 + ql]);
            A[mi][2] = fu(ws[r * 132 + k0 + 4 + ql]);
            A[mi][3] = fu(ws[(r + 8) * 132 + k0 + 4 + ql]);
        }
#pragma unroll
        for (int ni = 0; ni < 4; ++ni) {
            int cb = col0 + ni * 8 + qr;
            uint32_t b0 = fu(xT[cb * 132 + k0 + ql]);
            uint32_t b1 = fu(xT[cb * 132 + k0 + 4 + ql]);
            mma8(acc[0][ni], A[0][0], A[0][1], A[0][2], A[0][3], b0, b1);
            mma8(acc[1][ni], A[1][0], A[1][1], A[1][2], A[1][3], b0, b1);
        }
    }

    if (rg == 0) {
#pragma unroll
        for (int mi = 0; mi < 2; ++mi) {
            int d = mi * 16 + qr;
#pragma unroll
            for (int ni = 0; ni < 4; ++ni) {
                int col = col0 + ni * 8 + 2 * ql;
                qb[d * 129 + col]           = acc[mi][ni][0] * SQRT_LOG2E;
                qb[d * 129 + col + 1]       = acc[mi][ni][1] * SQRT_LOG2E;
                qb[(d + 8) * 129 + col]     = acc[mi][ni][2] * SQRT_LOG2E;
                qb[(d + 8) * 129 + col + 1] = acc[mi][ni][3] * SQRT_LOG2E;
            }
        }
    } else {
#pragma unroll
        for (int mi = 0; mi < 2; ++mi) {
            int rv = row0 - DD + mi * 16 + qr;
            float b0v = bv_s[rv], b1v = bv_s[rv + 8];
#pragma unroll
            for (int ni = 0; ni < 4; ++ni) {
                int col = col0 + ni * 8 + 2 * ql;
                *(half2*)&g_v[((size_t)b * CC + rv) * NN + n0 + col] =
                    __floats2half2_rn(acc[mi][ni][0] + b0v, acc[mi][ni][1] + b0v);
                *(half2*)&g_v[((size_t)b * CC + rv + 8) * NN + n0 + col] =
                    __floats2half2_rn(acc[mi][ni][2] + b1v, acc[mi][ni][3] + b1v);
            }
        }
    }
    __syncthreads();
    for (int i = tid; i < 128 * 16; i += 640) {
        int n = i >> 4, d2 = (i & 15) << 1;
        *(half2*)&g_qh[((size_t)b * NN + n0 + n) * DD + d2] =
            __floats2half2_rn(qb[d2 * 129 + n], qb[(d2 + 1) * 129 + n]);
    }
}

// ======================================================================
// k2: rl[n] = log2( sum_m exp2(E[n,m]) ), E via fp16 mma + ldmatrix.
// 512 threads, 2 CTAs/SM, double-buffered qm via cp.async.
// ======================================================================
__global__ __launch_bounds__(512, 2) void k_rowsum() {
    extern __shared__ float sm[];
    float*  red  = sm;                          // 128 f
    __half* qn_h = (__half*)(sm + 128);         // stride 40
    __half* qm0  = qn_h + 128 * 40;
    __half* qm1  = qm0 + 128 * 40;

    const int tid = threadIdx.x, w = tid >> 5, lane = tid & 31;
    const int row0 = (w & 3) * 32, col0 = (w >> 2) * 32;
    const int b = blockIdx.y, n0 = blockIdx.x * 128;
    const uint32_t qn_u = smem_u32(qn_h), qm0u = smem_u32(qm0), qm1u = smem_u32(qm1);
    const int la = ((lane >> 3) & 1) * 8 + (lane & 7);   // A: row offset
    const int lc = (lane >> 4) * 8;                      // A: col offset
    const int lbr = (lane >> 4) * 8 + (lane & 7);        // B: row offset
    const int lbc = ((lane >> 3) & 1) * 8;               // B: col offset

    if (tid < 128) red[tid] = 0.f;
    {
        int r = tid >> 2, j = (tid & 3) << 3;
        cpa16(qn_u + (r * 40 + j) * 2, &g_qh[((size_t)b * NN + n0 + r) * DD + j]);
    }
    CPA_COMMIT();
    {
        int r = tid >> 2, j = (tid & 3) << 3;
        cpa16(qm0u + (r * 40 + j) * 2, &g_qh[((size_t)b * NN + r) * DD + j]);
    }
    CPA_COMMIT();

    float racc[2][2] = {};
    for (int mt = 0; mt < NN / 128; ++mt) {
        const uint32_t qmu = (mt & 1) ? qm1u : qm0u;
        const uint32_t qmnu = (mt & 1) ? qm0u : qm1u;
        CPA_WAIT(0);
        __syncthreads();
        if (mt + 1 < NN / 128) {
            int r = tid >> 2, j = (tid & 3) << 3;
            cpa16(qmnu + (r * 40 + j) * 2,
                  &g_qh[((size_t)b * NN + (mt + 1) * 128 + r) * DD + j]);
            CPA_COMMIT();
        }

        float e[2][4][4] = {};
#pragma unroll
        for (int ks = 0; ks < 2; ++ks) {
            const int k0 = ks * 16;
            uint32_t A[2][4], Bp[2][4];
#pragma unroll
            for (int mi = 0; mi < 2; ++mi)
                ldsm4(A[mi], qn_u + ((row0 + mi * 16 + la) * 40 + k0 + lc) * 2);
#pragma unroll
            for (int p = 0; p < 2; ++p)
                ldsm4(Bp[p], qmu + ((col0 + p * 16 + lbr) * 40 + k0 + lbc) * 2);
#pragma unroll
            for (int mi = 0; mi < 2; ++mi)
#pragma unroll
                for (int ni = 0; ni < 4; ++ni)
                    mma16h(e[mi][ni], A[mi][0], A[mi][1], A[mi][2], A[mi][3],
                           Bp[ni >> 1][(ni & 1) * 2], Bp[ni >> 1][(ni & 1) * 2 + 1]);
        }
#pragma unroll
        for (int mi = 0; mi < 2; ++mi)
#pragma unroll
            for (int ni = 0; ni < 4; ++ni) {
                racc[mi][0] += ex2f(e[mi][ni][0]) + ex2f(e[mi][ni][1]);
                racc[mi][1] += ex2f(e[mi][ni][2]) + ex2f(e[mi][ni][3]);
            }
    }

    const int qr = lane >> 2, ql = lane & 3;
#pragma unroll
    for (int mi = 0; mi < 2; ++mi)
#pragma unroll
        for (int h = 0; h < 2; ++h) {
            float v = racc[mi][h];
            v += __shfl_xor_sync(0xffffffffu, v, 1);
            v += __shfl_xor_sync(0xffffffffu, v, 2);
            racc[mi][h] = v;
        }
    if (ql == 0) {
        atomicAdd(&red[row0 + qr],          racc[0][0]);
        atomicAdd(&red[row0 + qr + 8],      racc[0][1]);
        atomicAdd(&red[row0 + 16 + qr],     racc[1][0]);
        atomicAdd(&red[row0 + 16 + qr + 8], racc[1][1]);
    }
    __syncthreads();
    if (tid < 128) g_rl[(size_t)b * NN + n0 + tid] = lg2f(red[tid]);
}

// ======================================================================
// k3: fused attention + epilogue. 512 threads, 128x128 tiles.
// E fp16 (ldmatrix + mma16h); p = exp2(e - rl) stored [n][m] fp16;
// Y fp16 via ldmatrix(.trans); epilogue t = wt@xm tf32.
// smem bytes:
//   header 640f @0 (2560)
//   qm_h @2560  (128x40 h = 10240)
//   qn_h @12800 (10240)
//   vs_h @23040 (128x136 h = 34816)   } epilogue overlay:
//   pn_h @57856 (34816)               } xmT fp32 128x132 @23040
//   total 92672 B
// ======================================================================
__global__ __launch_bounds__(512, 1) void k_attn(const float* __restrict__ x,
                                                 const float* __restrict__ wt,
                                                 const float* __restrict__ bt,
                                                 const float* __restrict__ gamma,
                                                 const float* __restrict__ beta,
                                                 const float* __restrict__ mean,
                                                 const float* __restrict__ var,
                                                 float* __restrict__ out) {
    extern __shared__ float sm[];
    char* smc = (char*)sm;
    float* csum_s = sm;             // 128
    float* cinv_s = sm + 128;
    float* A_s    = sm + 256;
    float* S_s    = sm + 384;
    float* rl_s   = sm + 512;
    __half* qm_h  = (__half*)(smc + 2560);    // stride 40
    __half* qn_h  = (__half*)(smc + 12800);   // stride 40
    __half* vs_h  = (__half*)(smc + 23040);   // [c][n] stride 136
    __half* pn_h  = (__half*)(smc + 57856);   // [n][m] stride 136
    float*  xmT   = (float*)(smc + 23040);    // epilogue overlay, stride 132

    const int tid = threadIdx.x, w = tid >> 5, lane = tid & 31;
    const int row0 = (w & 3) * 32, col0 = (w >> 2) * 32;
    const int qr = lane >> 2, ql = lane & 3;
    const int b = blockIdx.y, m0 = blockIdx.x * 128;
    const uint32_t qm_u = smem_u32(qm_h), qn_u = smem_u32(qn_h);
    const uint32_t vs_u = smem_u32(vs_h), pn_u = smem_u32(pn_h);
    const int la = ((lane >> 3) & 1) * 8 + (lane & 7);
    const int lc = (lane >> 4) * 8;
    const int lbr = (lane >> 4) * 8 + (lane & 7);
    const int lbc = ((lane >> 3) & 1) * 8;

    if (tid < 128) {
        csum_s[tid] = 0.f;
        float A = gamma[tid] * rsqrtf(var[tid] + 1e-5f);
        A_s[tid] = A;
        S_s[tid] = beta[tid] + (bt[tid] - mean[tid]) * A;
    }
    {   // qm: once per block, plain vector loads
        int r = tid >> 2, j = (tid & 3) << 3;
        *(uint4*)&qm_h[r * 40 + j] =
            *(const uint4*)&g_qh[((size_t)b * NN + m0 + r) * DD + j];
    }
    // prologue prefetch: qn(0), vs(0)
    {
        int r = tid >> 2, j = (tid & 3) << 3;
        cpa16(qn_u + (r * 40 + j) * 2, &g_qh[((size_t)b * NN + r) * DD + j]);
    }
    CPA_COMMIT();
#pragma unroll
    for (int k = 0; k < 4; ++k) {
        int idx8 = tid + k * 512;
        int c = idx8 >> 4, j = (idx8 & 15) << 3;
        cpa16(vs_u + (c * 136 + j) * 2, &g_v[((size_t)b * CC + c) * NN + j]);
    }
    CPA_COMMIT();

    float yacc[2][4][4] = {};
    float csum[8] = {};

    for (int nt = 0; nt < NN / 128; ++nt) {
        const int nb = nt * 128;
        if (tid < 128) rl_s[tid] = g_rl[(size_t)b * NN + nb + tid];
        CPA_WAIT(1);                 // qn(nt) ready
        __syncthreads();

        // ---- E = qn . qm^T (fp16 ldmatrix + mma16h) ----
        float e[2][4][4] = {};
#pragma unroll
        for (int ks = 0; ks < 2; ++ks) {
            const int k0 = ks * 16;
            uint32_t A[2][4], Bp[2][4];
#pragma unroll
            for (int mi = 0; mi < 2; ++mi)
                ldsm4(A[mi], qn_u + ((row0 + mi * 16 + la) * 40 + k0 + lc) * 2);
#pragma unroll
            for (int p = 0; p < 2; ++p)
                ldsm4(Bp[p], qm_u + ((col0 + p * 16 + lbr) * 40 + k0 + lbc) * 2);
#pragma unroll
            for (int mi = 0; mi < 2; ++mi)
#pragma unroll
                for (int ni = 0; ni < 4; ++ni)
                    mma16h(e[mi][ni], A[mi][0], A[mi][1], A[mi][2], A[mi][3],
                           Bp[ni >> 1][(ni & 1) * 2], Bp[ni >> 1][(ni & 1) * 2 + 1]);
        }

        // ---- p = exp2(e - rl[n]); csum; store [n][m] fp16 half2 ----
#pragma unroll
        for (int mi = 0; mi < 2; ++mi) {
            int r = row0 + mi * 16 + qr;
            float rl0 = rl_s[r], rl1 = rl_s[r + 8];
#pragma unroll
            for (int ni = 0; ni < 4; ++ni) {
                int col = col0 + ni * 8 + 2 * ql;
                float p00 = ex2f(e[mi][ni][0] - rl0);
                float p01 = ex2f(e[mi][ni][1] - rl0);
                float p10 = ex2f(e[mi][ni][2] - rl1);
                float p11 = ex2f(e[mi][ni][3] - rl1);
                csum[ni * 2]     += p00 + p10;
                csum[ni * 2 + 1] += p01 + p11;
                *(half2*)&pn_h[r * 136 + col]       = __floats2half2_rn(p00, p01);
                *(half2*)&pn_h[(r + 8) * 136 + col] = __floats2half2_rn(p10, p11);
            }
        }
        CPA_WAIT(0);                 // vs(nt) ready
        __syncthreads();             // pn visible; qn reads done

        if (nt + 1 < NN / 128) {     // prefetch qn(nt+1) during Y-mma
            int r = tid >> 2, j = (tid & 3) << 3;
            cpa16(qn_u + (r * 40 + j) * 2,
                  &g_qh[((size_t)b * NN + nb + 128 + r) * DD + j]);
            CPA_COMMIT();
        }

        // ---- Y += v @ p (fp16, ldmatrix) ----
#pragma unroll
        for (int ks = 0; ks < 8; ++ks) {
            const int k0 = ks * 16;
            uint32_t A[2][4], Bp[2][4];
#pragma unroll
            for (int mi = 0; mi < 2; ++mi)
                ldsm4(A[mi], vs_u + ((row0 + mi * 16 + la) * 136 + k0 + lc) * 2);
#pragma unroll
            for (int p = 0; p < 2; ++p)
                ldsm4t(Bp[p], pn_u + ((k0 + la) * 136 + col0 + p * 16 + lc) * 2);
#pragma unroll
            for (int mi = 0; mi < 2; ++mi)
#pragma unroll
                for (int ni = 0; ni < 4; ++ni)
                    mma16h(yacc[mi][ni], A[mi][0], A[mi][1], A[mi][2], A[mi][3],
                           Bp[ni >> 1][(ni & 1) * 2], Bp[ni >> 1][(ni & 1) * 2 + 1]);
        }
        __syncthreads();             // vs/pn reads done
        if (nt + 1 < NN / 128) {     // prefetch vs(nt+1) during next E+exp
#pragma unroll
            for (int k = 0; k < 4; ++k) {
                int idx8 = tid + k * 512;
                int c = idx8 >> 4, j = (idx8 & 15) << 3;
                cpa16(vs_u + (c * 136 + j) * 2,
                      &g_v[((size_t)b * CC + c) * NN + nb + 128 + j]);
            }
            CPA_COMMIT();
        }
    }

    // ---------------- epilogue ----------------
#pragma unroll
    for (int i = 0; i < 8; ++i) {
        float v = csum[i];
        v += __shfl_xor_sync(0xffffffffu, v, 4);
        v += __shfl_xor_sync(0xffffffffu, v, 8);
        v += __shfl_xor_sync(0xffffffffu, v, 16);
        if (qr == 0) atomicAdd(&csum_s[col0 + (i >> 1) * 8 + 2 * ql + (i & 1)], v);
    }
    __syncthreads();
    if (tid < 128) cinv_s[tid] = 1.0f / (1e-9f + csum_s[tid]);
    __syncthreads();

    // xmT[m][c] = x - Y*cinv  (fp32 overlay, stride 132)
    const float* xb = x + ((size_t)b * CC) * NN + m0;
#pragma unroll
    for (int mi = 0; mi < 2; ++mi) {
        int r = row0 + mi * 16 + qr;
#pragma unroll
        for (int ni = 0; ni < 4; ++ni) {
            int col = col0 + ni * 8 + 2 * ql;
            float2 x0 = __ldg((const float2*)&xb[(size_t)r * NN + col]);
            float2 x1 = __ldg((const float2*)&xb[(size_t)(r + 8) * NN + col]);
            float ci0 = cinv_s[col], ci1 = cinv_s[col + 1];
            xmT[col * 132 + r]           = to_tf32(x0.x - yacc[mi][ni][0] * ci0);
            xmT[(col + 1) * 132 + r]     = to_tf32(x0.y - yacc[mi][ni][1] * ci1);
            xmT[col * 132 + r + 8]       = to_tf32(x1.x - yacc[mi][ni][2] * ci0);
            xmT[(col + 1) * 132 + r + 8] = to_tf32(x1.y - yacc[mi][ni][3] * ci1);
        }
    }
    __syncthreads();

    // t = wt @ xm  (tf32; wt fragments from gmem, L2-resident)
    float tacc[2][4][4] = {};
#pragma unroll
    for (int ks = 0; ks < 16; ++ks) {
        const int k0 = ks * 8;
        uint32_t A[2][4];
#pragma unroll
        for (int mi = 0; mi < 2; ++mi) {
            int r = row0 + mi * 16 + qr;
            A[mi][0] = fu(to_tf32(__ldg(&wt[r * CC + k0 + ql])));
            A[mi][1] = fu(to_tf32(__ldg(&wt[(r + 8) * CC + k0 + ql])));
            A[mi][2] = fu(to_tf32(__ldg(&wt[r * CC + k0 + 4 + ql])));
            A[mi][3] = fu(to_tf32(__ldg(&wt[(r + 8) * CC + k0 + 4 + ql])));
        }
#pragma unroll
        for (int ni = 0; ni < 4; ++ni) {
            int cb = col0 + ni * 8 + qr;
            uint32_t b0 = fu(xmT[cb * 132 + k0 + ql]);
            uint32_t b1 = fu(xmT[cb * 132 + k0 + 4 + ql]);
            mma8(tacc[0][ni], A[0][0], A[0][1], A[0][2], A[0][3], b0, b1);
            mma8(tacc[1][ni], A[1][0], A[1][1], A[1][2], A[1][3], b0, b1);
        }
    }

    // out = x + relu(t*A + S)
#pragma unroll
    for (int mi = 0; mi < 2; ++mi) {
        int r = row0 + mi * 16 + qr;
        float a0 = A_s[r], s0 = S_s[r];
        float a1 = A_s[r + 8], s1 = S_s[r + 8];
#pragma unroll
        for (int ni = 0; ni < 4; ++ni) {
            int col = col0 + ni * 8 + 2 * ql;
            float2 x0 = __ldg((const float2*)&xb[(size_t)r * NN + col]);
            float2 x1 = __ldg((const float2*)&xb[(size_t)(r + 8) * NN + col]);
            float2 o0, o1;
            o0.x = x0.x + fmaxf(fmaf(tacc[mi][ni][0], a0, s0), 0.f);
            o0.y = x0.y + fmaxf(fmaf(tacc[mi][ni][1], a0, s0), 0.f);
            o1.x = x1.x + fmaxf(fmaf(tacc[mi][ni][2], a1, s1), 0.f);
            o1.y = x1.y + fmaxf(fmaf(tacc[mi][ni][3], a1, s1), 0.f);
            *(float2*)&out[((size_t)b * CC + r) * NN + m0 + col]     = o0;
            *(float2*)&out[((size_t)b * CC + r + 8) * NN + m0 + col] = o1;
        }
    }
}

// ======================================================================
extern "C" void kernel_launch(void* const* d_in, const int* in_sizes, int n_in,
                              void* d_out, int out_size) {
    const float* x     = (const float*)d_in[0];
    const float* wq    = (const float*)d_in[1];
    const float* wv    = (const float*)d_in[2];
    const float* bv    = (const float*)d_in[3];
    const float* wt    = (const float*)d_in[4];
    const float* bt    = (const float*)d_in[5];
    const float* gamma = (const float*)d_in[6];
    const float* beta  = (const float*)d_in[7];
    const float* mean  = (const float*)d_in[8];
    const float* var   = (const float*)d_in[9];
    float* out = (float*)d_out;

    const int S1 = (16896 + 21120 + 4128 + 128) * 4;   // 169088
    const int S2 = 128 * 4 + 3 * 128 * 40 * 2;         // 31232
    const int S3 = 92672;

    cudaFuncSetAttribute(k_qv,     cudaFuncAttributeMaxDynamicSharedMemorySize, S1);
    cudaFuncSetAttribute(k_rowsum, cudaFuncAttributeMaxDynamicSharedMemorySize, S2);
    cudaFuncSetAttribute(k_attn,   cudaFuncAttributeMaxDynamicSharedMemorySize, S3);

    k_qv<<<dim3(16, 16), 640, S1>>>(x, wq, wv, bv);
    k_rowsum<<<dim3(16, 16), 512, S2>>>();
    k_attn<<<dim3(16, 16), 512, S3>>>(x, wt, bt, gamma, beta, mean, var, out);
}

// round 9
// speedup vs baseline: 1.7472x; 1.0422x over previous
#include <cuda_runtime.h>
#include <cuda_fp16.h>
#include <cstdint>

#define BB 16
#define CC 128
#define DD 32
#define NN 2048
#define SQRT_LOG2E 1.2011224087864498f

// ---------------- device scratch (static) ----------------
__device__ __half g_qh[BB * NN * DD];   // qT[b][n][d], *sqrt(log2e), fp16
__device__ __half g_v [BB * CC * NN];   // v[b][c][n], fp16
__device__ float  g_rl[BB * NN];        // log2(rowsum)

// ---------------- helpers ----------------
__device__ __forceinline__ float to_tf32(float x) {
    uint32_t u; asm("cvt.rna.tf32.f32 %0, %1;" : "=r"(u) : "f"(x));
    return __uint_as_float(u);
}
__device__ __forceinline__ float ex2f(float x) {
    float y; asm("ex2.approx.ftz.f32 %0, %1;" : "=f"(y) : "f"(x)); return y;
}
__device__ __forceinline__ float lg2f(float x) {
    float y; asm("lg2.approx.f32 %0, %1;" : "=f"(y) : "f"(x)); return y;
}
__device__ __forceinline__ void mma8(float c[4],
                                     uint32_t a0, uint32_t a1, uint32_t a2, uint32_t a3,
                                     uint32_t b0, uint32_t b1) {
    asm volatile(
        "mma.sync.aligned.m16n8k8.row.col.f32.tf32.tf32.f32 "
        "{%0,%1,%2,%3}, {%4,%5,%6,%7}, {%8,%9}, {%0,%1,%2,%3};"
        : "+f"(c[0]), "+f"(c[1]), "+f"(c[2]), "+f"(c[3])
        : "r"(a0), "r"(a1), "r"(a2), "r"(a3), "r"(b0), "r"(b1));
}
__device__ __forceinline__ void mma16h(float c[4],
                                       uint32_t a0, uint32_t a1, uint32_t a2, uint32_t a3,
                                       uint32_t b0, uint32_t b1) {
    asm volatile(
        "mma.sync.aligned.m16n8k16.row.col.f32.f16.f16.f32 "
        "{%0,%1,%2,%3}, {%4,%5,%6,%7}, {%8,%9}, {%0,%1,%2,%3};"
        : "+f"(c[0]), "+f"(c[1]), "+f"(c[2]), "+f"(c[3])
        : "r"(a0), "r"(a1), "r"(a2), "r"(a3), "r"(b0), "r"(b1));
}
__device__ __forceinline__ void ldsm4(uint32_t r[4], uint32_t addr) {
    asm volatile("ldmatrix.sync.aligned.m8n8.x4.shared.b16 {%0,%1,%2,%3}, [%4];"
        : "=r"(r[0]), "=r"(r[1]), "=r"(r[2]), "=r"(r[3]) : "r"(addr));
}
__device__ __forceinline__ void ldsm4t(uint32_t r[4], uint32_t addr) {
    asm volatile("ldmatrix.sync.aligned.m8n8.x4.trans.shared.b16 {%0,%1,%2,%3}, [%4];"
        : "=r"(r[0]), "=r"(r[1]), "=r"(r[2]), "=r"(r[3]) : "r"(addr));
}
__device__ __forceinline__ uint32_t fu(float f) { return __float_as_uint(f); }
__device__ __forceinline__ uint32_t smem_u32(const void* p) {
    uint32_t a;
    asm("{ .reg .u64 t; cvta.to.shared.u64 t, %1; cvt.u32.u64 %0, t; }" : "=r"(a) : "l"(p));
    return a;
}
__device__ __forceinline__ void cpa16(uint32_t dst, const void* src) {
    asm volatile("cp.async.cg.shared.global [%0], [%1], 16;" :: "r"(dst), "l"(src));
}
#define CPA_COMMIT() asm volatile("cp.async.commit_group;" ::: "memory")
#define CPA_WAIT(n)  asm volatile("cp.async.wait_group %0;" :: "n"(n) : "memory")

// ======================================================================
// k1: q = wq@x (scaled, fp16) ; v = wv@x + bv (fp16) — fp16 mma compute
// 640 threads (20 warps, 32x32 warp tiles on a 160x128 output).
// smem: xh 128x136 h (34816B) @0; wsh 160x136 h (43520B) @34816;
//       qb 32x129 f (16512B) @78336; bv_s 128 f @94848; total 95360B
// ======================================================================
__global__ __launch_bounds__(640) void k_qv(const float* __restrict__ x,
                                            const float* __restrict__ wq,
                                            const float* __restrict__ wv,
                                            const float* __restrict__ bv) {
    extern __shared__ char smc[];
    __half* xh   = (__half*)smc;              // [n][c] stride 136
    __half* wsh  = (__half*)(smc + 34816);    // [r][c] stride 136
    float*  qb   = (float*)(smc + 78336);     // 32x129
    float*  bv_s = (float*)(smc + 94848);
    const int b  = blockIdx.y;
    const int n0 = blockIdx.x * 128;
    const int tid = threadIdx.x;
    const float* xb = x + (size_t)b * CC * NN;

    for (int i = tid; i < CC * 128; i += 640) {
        int c = i >> 7, n = i & 127;
        xh[n * 136 + c] = __float2half_rn(xb[(size_t)c * NN + n0 + n]);
    }
    for (int i = tid; i < 160 * 128; i += 640) {
        int r = i >> 7, c = i & 127;
        float w = (r < DD) ? wq[r * CC + c] : wv[(r - DD) * CC + c];
        wsh[r * 136 + c] = __float2half_rn(w);
    }
    if (tid < CC) bv_s[tid] = bv[tid];
    __syncthreads();

    const int w = tid >> 5, lane = tid & 31;
    const int rg = w >> 2, cg = w & 3;
    const int row0 = rg * 32, col0 = cg * 32;
    const int qr = lane >> 2, ql = lane & 3;
    const uint32_t ws_u = smem_u32(wsh), xh_u = smem_u32(xh);
    const int la = ((lane >> 3) & 1) * 8 + (lane & 7);
    const int lc = (lane >> 4) * 8;
    const int lbr = (lane >> 4) * 8 + (lane & 7);
    const int lbc = ((lane >> 3) & 1) * 8;

    float acc[2][4][4] = {};
#pragma unroll
    for (int ks = 0; ks < 8; ++ks) {
        const int k0 = ks * 16;
        uint32_t A[2][4], Bp[2][4];
#pragma unroll
        for (int mi = 0; mi < 2; ++mi)
            ldsm4(A[mi], ws_u + ((row0 + mi * 16 + la) * 136 + k0 + lc) * 2);
#pragma unroll
        for (int p = 0; p < 2; ++p)
            ldsm4(Bp[p], xh_u + ((col0 + p * 16 + lbr) * 136 + k0 + lbc) * 2);
#pragma unroll
        for (int mi = 0; mi < 2; ++mi)
#pragma unroll
            for (int ni = 0; ni < 4; ++ni)
                mma16h(acc[mi][ni], A[mi][0], A[mi][1], A[mi][2], A[mi][3],
                       Bp[ni >> 1][(ni & 1) * 2], Bp[ni >> 1][(ni & 1) * 2 + 1]);
    }

    if (rg == 0) {
#pragma unroll
        for (int mi = 0; mi < 2; ++mi) {
            int d = mi * 16 + qr;
#pragma unroll
            for (int ni = 0; ni < 4; ++ni) {
                int col = col0 + ni * 8 + 2 * ql;
                qb[d * 129 + col]           = acc[mi][ni][0] * SQRT_LOG2E;
                qb[d * 129 + col + 1]       = acc[mi][ni][1] * SQRT_LOG2E;
                qb[(d + 8) * 129 + col]     = acc[mi][ni][2] * SQRT_LOG2E;
                qb[(d + 8) * 129 + col + 1] = acc[mi][ni][3] * SQRT_LOG2E;
            }
        }
    } else {
#pragma unroll
        for (int mi = 0; mi < 2; ++mi) {
            int rv = row0 - DD + mi * 16 + qr;
            float b0v = bv_s[rv], b1v = bv_s[rv + 8];
#pragma unroll
            for (int ni = 0; ni < 4; ++ni) {
                int col = col0 + ni * 8 + 2 * ql;
                *(half2*)&g_v[((size_t)b * CC + rv) * NN + n0 + col] =
                    __floats2half2_rn(acc[mi][ni][0] + b0v, acc[mi][ni][1] + b0v);
                *(half2*)&g_v[((size_t)b * CC + rv + 8) * NN + n0 + col] =
                    __floats2half2_rn(acc[mi][ni][2] + b1v, acc[mi][ni][3] + b1v);
            }
        }
    }
    __syncthreads();
    for (int i = tid; i < 128 * 16; i += 640) {
        int n = i >> 4, d2 = (i & 15) << 1;
        *(half2*)&g_qh[((size_t)b * NN + n0 + n) * DD + d2] =
            __floats2half2_rn(qb[d2 * 129 + n], qb[(d2 + 1) * 129 + n]);
    }
}

// ======================================================================
// k2: rl[n] = log2( sum_m exp2(E[n,m]) ), E via fp16 mma + ldmatrix.
// 512 threads, 2 CTAs/SM, double-buffered qm via cp.async.
// ======================================================================
__global__ __launch_bounds__(512, 2) void k_rowsum() {
    extern __shared__ float sm[];
    float*  red  = sm;                          // 128 f
    __half* qn_h = (__half*)(sm + 128);         // stride 40
    __half* qm0  = qn_h + 128 * 40;
    __half* qm1  = qm0 + 128 * 40;

    const int tid = threadIdx.x, w = tid >> 5, lane = tid & 31;
    const int row0 = (w & 3) * 32, col0 = (w >> 2) * 32;
    const int b = blockIdx.y, n0 = blockIdx.x * 128;
    const uint32_t qn_u = smem_u32(qn_h), qm0u = smem_u32(qm0), qm1u = smem_u32(qm1);
    const int la = ((lane >> 3) & 1) * 8 + (lane & 7);
    const int lc = (lane >> 4) * 8;
    const int lbr = (lane >> 4) * 8 + (lane & 7);
    const int lbc = ((lane >> 3) & 1) * 8;

    if (tid < 128) red[tid] = 0.f;
    {
        int r = tid >> 2, j = (tid & 3) << 3;
        cpa16(qn_u + (r * 40 + j) * 2, &g_qh[((size_t)b * NN + n0 + r) * DD + j]);
    }
    CPA_COMMIT();
    {
        int r = tid >> 2, j = (tid & 3) << 3;
        cpa16(qm0u + (r * 40 + j) * 2, &g_qh[((size_t)b * NN + r) * DD + j]);
    }
    CPA_COMMIT();

    float racc[2][2] = {};
    for (int mt = 0; mt < NN / 128; ++mt) {
        const uint32_t qmu = (mt & 1) ? qm1u : qm0u;
        const uint32_t qmnu = (mt & 1) ? qm0u : qm1u;
        CPA_WAIT(0);
        __syncthreads();
        if (mt + 1 < NN / 128) {
            int r = tid >> 2, j = (tid & 3) << 3;
            cpa16(qmnu + (r * 40 + j) * 2,
                  &g_qh[((size_t)b * NN + (mt + 1) * 128 + r) * DD + j]);
            CPA_COMMIT();
        }

        float e[2][4][4] = {};
#pragma unroll
        for (int ks = 0; ks < 2; ++ks) {
            const int k0 = ks * 16;
            uint32_t A[2][4], Bp[2][4];
#pragma unroll
            for (int mi = 0; mi < 2; ++mi)
                ldsm4(A[mi], qn_u + ((row0 + mi * 16 + la) * 40 + k0 + lc) * 2);
#pragma unroll
            for (int p = 0; p < 2; ++p)
                ldsm4(Bp[p], qmu + ((col0 + p * 16 + lbr) * 40 + k0 + lbc) * 2);
#pragma unroll
            for (int mi = 0; mi < 2; ++mi)
#pragma unroll
                for (int ni = 0; ni < 4; ++ni)
                    mma16h(e[mi][ni], A[mi][0], A[mi][1], A[mi][2], A[mi][3],
                           Bp[ni >> 1][(ni & 1) * 2], Bp[ni >> 1][(ni & 1) * 2 + 1]);
        }
#pragma unroll
        for (int mi = 0; mi < 2; ++mi)
#pragma unroll
            for (int ni = 0; ni < 4; ++ni) {
                racc[mi][0] += ex2f(e[mi][ni][0]) + ex2f(e[mi][ni][1]);
                racc[mi][1] += ex2f(e[mi][ni][2]) + ex2f(e[mi][ni][3]);
            }
    }

    const int qr = lane >> 2, ql = lane & 3;
#pragma unroll
    for (int mi = 0; mi < 2; ++mi)
#pragma unroll
        for (int h = 0; h < 2; ++h) {
            float v = racc[mi][h];
            v += __shfl_xor_sync(0xffffffffu, v, 1);
            v += __shfl_xor_sync(0xffffffffu, v, 2);
            racc[mi][h] = v;
        }
    if (ql == 0) {
        atomicAdd(&red[row0 + qr],          racc[0][0]);
        atomicAdd(&red[row0 + qr + 8],      racc[0][1]);
        atomicAdd(&red[row0 + 16 + qr],     racc[1][0]);
        atomicAdd(&red[row0 + 16 + qr + 8], racc[1][1]);
    }
    __syncthreads();
    if (tid < 128) g_rl[(size_t)b * NN + n0 + tid] = lg2f(red[tid]);
}

// ======================================================================
// k3: fused attention + epilogue. 256 threads, m-tile 64, n-tile 128,
// 2 CTAs/SM. 8 warps: row-groups (w&3)*32, col-groups (w>>2)*32 (2 of them).
// smem bytes:
//   header 640f @0 (2560)
//   qm_h @2560  (64x40 h = 5120)
//   qn_h @7680  (128x40 h = 10240)
//   vs_h @17920 (128x136 h = 34816)   } epilogue overlay:
//   pn_h @52736 (128x72 h = 18432)    } xmT fp32 64x132 @17920 (33792)
//   total 71168 B
// ======================================================================
__global__ __launch_bounds__(256, 2) void k_attn(const float* __restrict__ x,
                                                 const float* __restrict__ wt,
                                                 const float* __restrict__ bt,
                                                 const float* __restrict__ gamma,
                                                 const float* __restrict__ beta,
                                                 const float* __restrict__ mean,
                                                 const float* __restrict__ var,
                                                 float* __restrict__ out) {
    extern __shared__ float sm[];
    char* smc = (char*)sm;
    float* csum_s = sm;             // 64
    float* cinv_s = sm + 64;        // 64
    float* A_s    = sm + 128;       // 128
    float* S_s    = sm + 256;       // 128
    float* rl_s   = sm + 384;       // 128
    __half* qm_h  = (__half*)(smc + 2560);    // [m][d] stride 40, 64 rows
    __half* qn_h  = (__half*)(smc + 7680);    // [n][d] stride 40, 128 rows
    __half* vs_h  = (__half*)(smc + 17920);   // [c][n] stride 136
    __half* pn_h  = (__half*)(smc + 52736);   // [n][m] stride 72
    float*  xmT   = (float*)(smc + 17920);    // epilogue overlay, [m][c] stride 132

    const int tid = threadIdx.x, w = tid >> 5, lane = tid & 31;
    const int row0 = (w & 3) * 32, col0 = (w >> 2) * 32;   // col0 in {0,32}
    const int qr = lane >> 2, ql = lane & 3;
    const int b = blockIdx.y, m0 = blockIdx.x * 64;
    const uint32_t qm_u = smem_u32(qm_h), qn_u = smem_u32(qn_h);
    const uint32_t vs_u = smem_u32(vs_h), pn_u = smem_u32(pn_h);
    const int la = ((lane >> 3) & 1) * 8 + (lane & 7);
    const int lc = (lane >> 4) * 8;
    const int lbr = (lane >> 4) * 8 + (lane & 7);
    const int lbc = ((lane >> 3) & 1) * 8;

    if (tid < 64) csum_s[tid] = 0.f;
    if (tid >= 64 && tid < 192) {
        int c = tid - 64;
        float A = gamma[c] * rsqrtf(var[c] + 1e-5f);
        A_s[c] = A;
        S_s[c] = beta[c] + (bt[c] - mean[c]) * A;
    }
    {   // qm: 64 rows x 32 halves = 256 chunks of 8
        int r = tid >> 2, j = (tid & 3) << 3;
        *(uint4*)&qm_h[r * 40 + j] =
            *(const uint4*)&g_qh[((size_t)b * NN + m0 + r) * DD + j];
    }
    // prologue prefetch: qn(0) (512 chunks), vs(0) (2048 chunks)
#pragma unroll
    for (int k = 0; k < 2; ++k) {
        int idx = tid + k * 256;
        int r = idx >> 2, j = (idx & 3) << 3;
        cpa16(qn_u + (r * 40 + j) * 2, &g_qh[((size_t)b * NN + r) * DD + j]);
    }
    CPA_COMMIT();
#pragma unroll
    for (int k = 0; k < 8; ++k) {
        int idx = tid + k * 256;
        int c = idx >> 4, j = (idx & 15) << 3;
        cpa16(vs_u + (c * 136 + j) * 2, &g_v[((size_t)b * CC + c) * NN + j]);
    }
    CPA_COMMIT();

    float yacc[2][4][4] = {};
    float csum[8] = {};

    for (int nt = 0; nt < NN / 128; ++nt) {
        const int nb = nt * 128;
        if (tid < 128) rl_s[tid] = g_rl[(size_t)b * NN + nb + tid];
        CPA_WAIT(1);                 // qn(nt) ready
        __syncthreads();

        // ---- E = qn . qm^T (fp16): [n 128][m 64], warp 32x32 ----
        float e[2][4][4] = {};
#pragma unroll
        for (int ks = 0; ks < 2; ++ks) {
            const int k0 = ks * 16;
            uint32_t A[2][4], Bp[2][4];
#pragma unroll
            for (int mi = 0; mi < 2; ++mi)
                ldsm4(A[mi], qn_u + ((row0 + mi * 16 + la) * 40 + k0 + lc) * 2);
#pragma unroll
            for (int p = 0; p < 2; ++p)
                ldsm4(Bp[p], qm_u + ((col0 + p * 16 + lbr) * 40 + k0 + lbc) * 2);
#pragma unroll
            for (int mi = 0; mi < 2; ++mi)
#pragma unroll
                for (int ni = 0; ni < 4; ++ni)
                    mma16h(e[mi][ni], A[mi][0], A[mi][1], A[mi][2], A[mi][3],
                           Bp[ni >> 1][(ni & 1) * 2], Bp[ni >> 1][(ni & 1) * 2 + 1]);
        }

        // ---- p = exp2(e - rl[n]); csum; store [n][m] fp16 half2 ----
#pragma unroll
        for (int mi = 0; mi < 2; ++mi) {
            int r = row0 + mi * 16 + qr;
            float rl0 = rl_s[r], rl1 = rl_s[r + 8];
#pragma unroll
            for (int ni = 0; ni < 4; ++ni) {
                int col = col0 + ni * 8 + 2 * ql;
                float p00 = ex2f(e[mi][ni][0] - rl0);
                float p01 = ex2f(e[mi][ni][1] - rl0);
                float p10 = ex2f(e[mi][ni][2] - rl1);
                float p11 = ex2f(e[mi][ni][3] - rl1);
                csum[ni * 2]     += p00 + p10;
                csum[ni * 2 + 1] += p01 + p11;
                *(half2*)&pn_h[r * 72 + col]       = __floats2half2_rn(p00, p01);
                *(half2*)&pn_h[(r + 8) * 72 + col] = __floats2half2_rn(p10, p11);
            }
        }
        CPA_WAIT(0);                 // vs(nt) ready
        __syncthreads();             // pn visible; qn reads done

        if (nt + 1 < NN / 128) {     // prefetch qn(nt+1) during Y-mma
#pragma unroll
            for (int k = 0; k < 2; ++k) {
                int idx = tid + k * 256;
                int r = idx >> 2, j = (idx & 3) << 3;
                cpa16(qn_u + (r * 40 + j) * 2,
                      &g_qh[((size_t)b * NN + nb + 128 + r) * DD + j]);
            }
            CPA_COMMIT();
        }

        // ---- Y += v @ p (fp16): [c 128][m 64], warp 32x32, K=128 ----
#pragma unroll
        for (int ks = 0; ks < 8; ++ks) {
            const int k0 = ks * 16;
            uint32_t A[2][4], Bp[2][4];
#pragma unroll
            for (int mi = 0; mi < 2; ++mi)
                ldsm4(A[mi], vs_u + ((row0 + mi * 16 + la) * 136 + k0 + lc) * 2);
#pragma unroll
            for (int p = 0; p < 2; ++p)
                ldsm4t(Bp[p], pn_u + ((k0 + la) * 72 + col0 + p * 16 + lc) * 2);
#pragma unroll
            for (int mi = 0; mi < 2; ++mi)
#pragma unroll
                for (int ni = 0; ni < 4; ++ni)
                    mma16h(yacc[mi][ni], A[mi][0], A[mi][1], A[mi][2], A[mi][3],
                           Bp[ni >> 1][(ni & 1) * 2], Bp[ni >> 1][(ni & 1) * 2 + 1]);
        }
        __syncthreads();             // vs/pn reads done
        if (nt + 1 < NN / 128) {     // prefetch vs(nt+1) during next E+exp
#pragma unroll
            for (int k = 0; k < 8; ++k) {
                int idx = tid + k * 256;
                int c = idx >> 4, j = (idx & 15) << 3;
                cpa16(vs_u + (c * 136 + j) * 2,
                      &g_v[((size_t)b * CC + c) * NN + nb + 128 + j]);
            }
            CPA_COMMIT();
        }
    }

    // ---------------- epilogue ----------------
#pragma unroll
    for (int i = 0; i < 8; ++i) {
        float v = csum[i];
        v += __shfl_xor_sync(0xffffffffu, v, 4);
        v += __shfl_xor_sync(0xffffffffu, v, 8);
        v += __shfl_xor_sync(0xffffffffu, v, 16);
        if (qr == 0) atomicAdd(&csum_s[col0 + (i >> 1) * 8 + 2 * ql + (i & 1)], v);
    }
    __syncthreads();
    if (tid < 64) cinv_s[tid] = 1.0f / (1e-9f + csum_s[tid]);
    __syncthreads();

    // xmT[m][c] = x - Y*cinv  (fp32 overlay, stride 132)
    const float* xb = x + ((size_t)b * CC) * NN + m0;
#pragma unroll
    for (int mi = 0; mi < 2; ++mi) {
        int r = row0 + mi * 16 + qr;
#pragma unroll
        for (int ni = 0; ni < 4; ++ni) {
            int col = col0 + ni * 8 + 2 * ql;
            float2 x0 = __ldg((const float2*)&xb[(size_t)r * NN + col]);
            float2 x1 = __ldg((const float2*)&xb[(size_t)(r + 8) * NN + col]);
            float ci0 = cinv_s[col], ci1 = cinv_s[col + 1];
            xmT[col * 132 + r]           = to_tf32(x0.x - yacc[mi][ni][0] * ci0);
            xmT[(col + 1) * 132 + r]     = to_tf32(x0.y - yacc[mi][ni][1] * ci1);
            xmT[col * 132 + r + 8]       = to_tf32(x1.x - yacc[mi][ni][2] * ci0);
            xmT[(col + 1) * 132 + r + 8] = to_tf32(x1.y - yacc[mi][ni][3] * ci1);
        }
    }
    __syncthreads();

    // t = wt @ xm  (tf32; wt fragments from gmem, L2-resident)
    float tacc[2][4][4] = {};
#pragma unroll
    for (int ks = 0; ks < 16; ++ks) {
        const int k0 = ks * 8;
        uint32_t A[2][4];
#pragma unroll
        for (int mi = 0; mi < 2; ++mi) {
            int r = row0 + mi * 16 + qr;
            A[mi][0] = fu(to_tf32(__ldg(&wt[r * CC + k0 + ql])));
            A[mi][1] = fu(to_tf32(__ldg(&wt[(r + 8) * CC + k0 + ql])));
            A[mi][2] = fu(to_tf32(__ldg(&wt[r * CC + k0 + 4 + ql])));
            A[mi][3] = fu(to_tf32(__ldg(&wt[(r + 8) * CC + k0 + 4 + ql])));
        }
#pragma unroll
        for (int ni = 0; ni < 4; ++ni) {
            int cb = col0 + ni * 8 + qr;
            uint32_t b0 = fu(xmT[cb * 132 + k0 + ql]);
            uint32_t b1 = fu(xmT[cb * 132 + k0 + 4 + ql]);
            mma8(tacc[0][ni], A[0][0], A[0][1], A[0][2], A[0][3], b0, b1);
            mma8(tacc[1][ni], A[1][0], A[1][1], A[1][2], A[1][3], b0, b1);
        }
    }

    // out = x + relu(t*A + S)
#pragma unroll
    for (int mi = 0; mi < 2; ++mi) {
        int r = row0 + mi * 16 + qr;
        float a0 = A_s[r], s0 = S_s[r];
        float a1 = A_s[r + 8], s1 = S_s[r + 8];
#pragma unroll
        for (int ni = 0; ni < 4; ++ni) {
            int col = col0 + ni * 8 + 2 * ql;
            float2 x0 = __ldg((const float2*)&xb[(size_t)r * NN + col]);
            float2 x1 = __ldg((const float2*)&xb[(size_t)(r + 8) * NN + col]);
            float2 o0, o1;
            o0.x = x0.x + fmaxf(fmaf(tacc[mi][ni][0], a0, s0), 0.f);
            o0.y = x0.y + fmaxf(fmaf(tacc[mi][ni][1], a0, s0), 0.f);
            o1.x = x1.x + fmaxf(fmaf(tacc[mi][ni][2], a1, s1), 0.f);
            o1.y = x1.y + fmaxf(fmaf(tacc[mi][ni][3], a1, s1), 0.f);
            *(float2*)&out[((size_t)b * CC + r) * NN + m0 + col]     = o0;
            *(float2*)&out[((size_t)b * CC + r + 8) * NN + m0 + col] = o1;
        }
    }
}

// ======================================================================
extern "C" void kernel_launch(void* const* d_in, const int* in_sizes, int n_in,
                              void* d_out, int out_size) {
    const float* x     = (const float*)d_in[0];
    const float* wq    = (const float*)d_in[1];
    const float* wv    = (const float*)d_in[2];
    const float* bv    = (const float*)d_in[3];
    const float* wt    = (const float*)d_in[4];
    const float* bt    = (const float*)d_in[5];
    const float* gamma = (const float*)d_in[6];
    const float* beta  = (const float*)d_in[7];
    const float* mean  = (const float*)d_in[8];
    const float* var   = (const float*)d_in[9];
    float* out = (float*)d_out;

    const int S1 = 95360;
    const int S2 = 128 * 4 + 3 * 128 * 40 * 2;   // 31232
    const int S3 = 71168;

    cudaFuncSetAttribute(k_qv,     cudaFuncAttributeMaxDynamicSharedMemorySize, S1);
    cudaFuncSetAttribute(k_rowsum, cudaFuncAttributeMaxDynamicSharedMemorySize, S2);
    cudaFuncSetAttribute(k_attn,   cudaFuncAttributeMaxDynamicSharedMemorySize, S3);

    k_qv<<<dim3(16, 16), 640, S1>>>(x, wq, wv, bv);
    k_rowsum<<<dim3(16, 16), 512, S2>>>();
    k_attn<<<dim3(32, 16), 256, S3>>>(x, wt, bt, gamma, beta, mean, var, out);
}

// round 10
// speedup vs baseline: 1.8654x; 1.0677x over previous
#include <cuda_runtime.h>
#include <cuda_fp16.h>
#include <cstdint>

#define BB 16
#define CC 128
#define DD 32
#define NN 2048
#define SQRT_LOG2E 1.2011224087864498f

// ---------------- device scratch (static) ----------------
__device__ __half g_qh[BB * NN * DD];   // qT[b][n][d], *sqrt(log2e), fp16
__device__ __half g_v [BB * CC * NN];   // v[b][c][n], fp16
__device__ float  g_rl[BB * NN];        // log2(rowsum)

// ---------------- helpers ----------------
__device__ __forceinline__ float ex2f(float x) {
    float y; asm("ex2.approx.ftz.f32 %0, %1;" : "=f"(y) : "f"(x)); return y;
}
__device__ __forceinline__ float lg2f(float x) {
    float y; asm("lg2.approx.f32 %0, %1;" : "=f"(y) : "f"(x)); return y;
}
__device__ __forceinline__ void mma16h(float c[4],
                                       uint32_t a0, uint32_t a1, uint32_t a2, uint32_t a3,
                                       uint32_t b0, uint32_t b1) {
    asm volatile(
        "mma.sync.aligned.m16n8k16.row.col.f32.f16.f16.f32 "
        "{%0,%1,%2,%3}, {%4,%5,%6,%7}, {%8,%9}, {%0,%1,%2,%3};"
        : "+f"(c[0]), "+f"(c[1]), "+f"(c[2]), "+f"(c[3])
        : "r"(a0), "r"(a1), "r"(a2), "r"(a3), "r"(b0), "r"(b1));
}
__device__ __forceinline__ void ldsm4(uint32_t r[4], uint32_t addr) {
    asm volatile("ldmatrix.sync.aligned.m8n8.x4.shared.b16 {%0,%1,%2,%3}, [%4];"
        : "=r"(r[0]), "=r"(r[1]), "=r"(r[2]), "=r"(r[3]) : "r"(addr));
}
__device__ __forceinline__ void ldsm4t(uint32_t r[4], uint32_t addr) {
    asm volatile("ldmatrix.sync.aligned.m8n8.x4.trans.shared.b16 {%0,%1,%2,%3}, [%4];"
        : "=r"(r[0]), "=r"(r[1]), "=r"(r[2]), "=r"(r[3]) : "r"(addr));
}
__device__ __forceinline__ uint32_t smem_u32(const void* p) {
    uint32_t a;
    asm("{ .reg .u64 t; cvta.to.shared.u64 t, %1; cvt.u32.u64 %0, t; }" : "=r"(a) : "l"(p));
    return a;
}
__device__ __forceinline__ void cpa16(uint32_t dst, const void* src) {
    asm volatile("cp.async.cg.shared.global [%0], [%1], 16;" :: "r"(dst), "l"(src));
}
#define CPA_COMMIT() asm volatile("cp.async.commit_group;" ::: "memory")
#define CPA_WAIT(n)  asm volatile("cp.async.wait_group %0;" :: "n"(n) : "memory")

// ======================================================================
// k1: q = wq@x (scaled, fp16) ; v = wv@x + bv (fp16) — fp16 mma compute
// 640 threads (20 warps, 32x32 warp tiles on a 160x128 output).
// smem: xh [c][n] 128x136 h @0 (34816); wsh [r][c] 160x136 h @34816 (43520);
//       qb 32x129 f @78336 (16512); bv_s @94848; total 95360B
// ======================================================================
__global__ __launch_bounds__(640) void k_qv(const float* __restrict__ x,
                                            const float* __restrict__ wq,
                                            const float* __restrict__ wv,
                                            const float* __restrict__ bv) {
    extern __shared__ char smc[];
    __half* xh   = (__half*)smc;              // [c][n] stride 136
    __half* wsh  = (__half*)(smc + 34816);    // [r][c] stride 136
    float*  qb   = (float*)(smc + 78336);     // 32x129
    float*  bv_s = (float*)(smc + 94848);
    const int b  = blockIdx.y;
    const int n0 = blockIdx.x * 128;
    const int tid = threadIdx.x;
    const float* xb = x + (size_t)b * CC * NN;

    // x staging: coalesced float2 reads, contiguous half2 writes ([c][n])
    for (int i = tid; i < CC * 64; i += 640) {
        int c = i >> 6, np = (i & 63) << 1;
        float2 xv = *(const float2*)&xb[(size_t)c * NN + n0 + np];
        *(half2*)&xh[c * 136 + np] = __floats2half2_rn(xv.x, xv.y);
    }
    for (int i = tid; i < 160 * 64; i += 640) {
        int r = i >> 6, cp = (i & 63) << 1;
        float2 wv2 = (r < DD) ? *(const float2*)&wq[r * CC + cp]
                              : *(const float2*)&wv[(r - DD) * CC + cp];
        *(half2*)&wsh[r * 136 + cp] = __floats2half2_rn(wv2.x, wv2.y);
    }
    if (tid < CC) bv_s[tid] = bv[tid];
    __syncthreads();

    const int w = tid >> 5, lane = tid & 31;
    const int rg = w >> 2, cg = w & 3;
    const int row0 = rg * 32, col0 = cg * 32;
    const int qr = lane >> 2, ql = lane & 3;
    const uint32_t ws_u = smem_u32(wsh), xh_u = smem_u32(xh);
    const int la = ((lane >> 3) & 1) * 8 + (lane & 7);
    const int lc = (lane >> 4) * 8;

    float acc[2][4][4] = {};
#pragma unroll
    for (int ks = 0; ks < 8; ++ks) {
        const int k0 = ks * 16;
        uint32_t A[2][4], Bp[2][4];
#pragma unroll
        for (int mi = 0; mi < 2; ++mi)
            ldsm4(A[mi], ws_u + ((row0 + mi * 16 + la) * 136 + k0 + lc) * 2);
#pragma unroll
        for (int p = 0; p < 2; ++p)
            ldsm4t(Bp[p], xh_u + ((k0 + la) * 136 + col0 + p * 16 + lc) * 2);
#pragma unroll
        for (int mi = 0; mi < 2; ++mi)
#pragma unroll
            for (int ni = 0; ni < 4; ++ni)
                mma16h(acc[mi][ni], A[mi][0], A[mi][1], A[mi][2], A[mi][3],
                       Bp[ni >> 1][(ni & 1) * 2], Bp[ni >> 1][(ni & 1) * 2 + 1]);
    }

    if (rg == 0) {
#pragma unroll
        for (int mi = 0; mi < 2; ++mi) {
            int d = mi * 16 + qr;
#pragma unroll
            for (int ni = 0; ni < 4; ++ni) {
                int col = col0 + ni * 8 + 2 * ql;
                qb[d * 129 + col]           = acc[mi][ni][0] * SQRT_LOG2E;
                qb[d * 129 + col + 1]       = acc[mi][ni][1] * SQRT_LOG2E;
                qb[(d + 8) * 129 + col]     = acc[mi][ni][2] * SQRT_LOG2E;
                qb[(d + 8) * 129 + col + 1] = acc[mi][ni][3] * SQRT_LOG2E;
            }
        }
    } else {
#pragma unroll
        for (int mi = 0; mi < 2; ++mi) {
            int rv = row0 - DD + mi * 16 + qr;
            float b0v = bv_s[rv], b1v = bv_s[rv + 8];
#pragma unroll
            for (int ni = 0; ni < 4; ++ni) {
                int col = col0 + ni * 8 + 2 * ql;
                *(half2*)&g_v[((size_t)b * CC + rv) * NN + n0 + col] =
                    __floats2half2_rn(acc[mi][ni][0] + b0v, acc[mi][ni][1] + b0v);
                *(half2*)&g_v[((size_t)b * CC + rv + 8) * NN + n0 + col] =
                    __floats2half2_rn(acc[mi][ni][2] + b1v, acc[mi][ni][3] + b1v);
            }
        }
    }
    __syncthreads();
    for (int i = tid; i < 128 * 16; i += 640) {
        int n = i >> 4, d2 = (i & 15) << 1;
        *(half2*)&g_qh[((size_t)b * NN + n0 + n) * DD + d2] =
            __floats2half2_rn(qb[d2 * 129 + n], qb[(d2 + 1) * 129 + n]);
    }
}

// ======================================================================
// k2: rl[n] = log2( sum_m exp2(E[n,m]) ), fp16 mma + ldmatrix.
// 512 threads, 2 CTAs/SM, double-buffered qm via cp.async.  (unchanged)
// ======================================================================
__global__ __launch_bounds__(512, 2) void k_rowsum() {
    extern __shared__ float sm[];
    float*  red  = sm;
    __half* qn_h = (__half*)(sm + 128);
    __half* qm0  = qn_h + 128 * 40;
    __half* qm1  = qm0 + 128 * 40;

    const int tid = threadIdx.x, w = tid >> 5, lane = tid & 31;
    const int row0 = (w & 3) * 32, col0 = (w >> 2) * 32;
    const int b = blockIdx.y, n0 = blockIdx.x * 128;
    const uint32_t qn_u = smem_u32(qn_h), qm0u = smem_u32(qm0), qm1u = smem_u32(qm1);
    const int la = ((lane >> 3) & 1) * 8 + (lane & 7);
    const int lc = (lane >> 4) * 8;
    const int lbr = (lane >> 4) * 8 + (lane & 7);
    const int lbc = ((lane >> 3) & 1) * 8;

    if (tid < 128) red[tid] = 0.f;
    {
        int r = tid >> 2, j = (tid & 3) << 3;
        cpa16(qn_u + (r * 40 + j) * 2, &g_qh[((size_t)b * NN + n0 + r) * DD + j]);
    }
    CPA_COMMIT();
    {
        int r = tid >> 2, j = (tid & 3) << 3;
        cpa16(qm0u + (r * 40 + j) * 2, &g_qh[((size_t)b * NN + r) * DD + j]);
    }
    CPA_COMMIT();

    float racc[2][2] = {};
    for (int mt = 0; mt < NN / 128; ++mt) {
        const uint32_t qmu = (mt & 1) ? qm1u : qm0u;
        const uint32_t qmnu = (mt & 1) ? qm0u : qm1u;
        CPA_WAIT(0);
        __syncthreads();
        if (mt + 1 < NN / 128) {
            int r = tid >> 2, j = (tid & 3) << 3;
            cpa16(qmnu + (r * 40 + j) * 2,
                  &g_qh[((size_t)b * NN + (mt + 1) * 128 + r) * DD + j]);
            CPA_COMMIT();
        }

        float e[2][4][4] = {};
#pragma unroll
        for (int ks = 0; ks < 2; ++ks) {
            const int k0 = ks * 16;
            uint32_t A[2][4], Bp[2][4];
#pragma unroll
            for (int mi = 0; mi < 2; ++mi)
                ldsm4(A[mi], qn_u + ((row0 + mi * 16 + la) * 40 + k0 + lc) * 2);
#pragma unroll
            for (int p = 0; p < 2; ++p)
                ldsm4(Bp[p], qmu + ((col0 + p * 16 + lbr) * 40 + k0 + lbc) * 2);
#pragma unroll
            for (int mi = 0; mi < 2; ++mi)
#pragma unroll
                for (int ni = 0; ni < 4; ++ni)
                    mma16h(e[mi][ni], A[mi][0], A[mi][1], A[mi][2], A[mi][3],
                           Bp[ni >> 1][(ni & 1) * 2], Bp[ni >> 1][(ni & 1) * 2 + 1]);
        }
#pragma unroll
        for (int mi = 0; mi < 2; ++mi)
#pragma unroll
            for (int ni = 0; ni < 4; ++ni) {
                racc[mi][0] += ex2f(e[mi][ni][0]) + ex2f(e[mi][ni][1]);
                racc[mi][1] += ex2f(e[mi][ni][2]) + ex2f(e[mi][ni][3]);
            }
    }

    const int qr = lane >> 2, ql = lane & 3;
#pragma unroll
    for (int mi = 0; mi < 2; ++mi)
#pragma unroll
        for (int h = 0; h < 2; ++h) {
            float v = racc[mi][h];
            v += __shfl_xor_sync(0xffffffffu, v, 1);
            v += __shfl_xor_sync(0xffffffffu, v, 2);
            racc[mi][h] = v;
        }
    if (ql == 0) {
        atomicAdd(&red[row0 + qr],          racc[0][0]);
        atomicAdd(&red[row0 + qr + 8],      racc[0][1]);
        atomicAdd(&red[row0 + 16 + qr],     racc[1][0]);
        atomicAdd(&red[row0 + 16 + qr + 8], racc[1][1]);
    }
    __syncthreads();
    if (tid < 128) g_rl[(size_t)b * NN + n0 + tid] = lg2f(red[tid]);
}

// ======================================================================
// k3: fused attention + epilogue. 256 threads, m-tile 64, n-tile 128,
// 2 CTAs/SM. vs double-buffered -> 2 barriers/iter. fp16 epilogue GEMM.
// smem bytes:
//   header @0 (2560): csum 64f, cinv 64f, A_s 128f, S_s 128f, rl_s 128f
//   qm_h @2560  (64x40 h  = 5120)
//   qn_h @7680  (128x40 h = 10240)
//   vs0  @17920 (128x136 h = 34816)   epi overlay: wt_h [cout][cin] str 136
//   vs1  @52736 (34816)               epi overlay: xm_h [m][c] str 136 (17408)
//   pn_h @87552 (128x72 h = 18432)
//   total 105984 B
// ======================================================================
__global__ __launch_bounds__(256, 2) void k_attn(const float* __restrict__ x,
                                                 const float* __restrict__ wt,
                                                 const float* __restrict__ bt,
                                                 const float* __restrict__ gamma,
                                                 const float* __restrict__ beta,
                                                 const float* __restrict__ mean,
                                                 const float* __restrict__ var,
                                                 float* __restrict__ out) {
    extern __shared__ float sm[];
    char* smc = (char*)sm;
    float* csum_s = sm;             // 64
    float* cinv_s = sm + 64;        // 64
    float* A_s    = sm + 128;       // 128
    float* S_s    = sm + 256;       // 128
    float* rl_s   = sm + 384;       // 128
    __half* qm_h  = (__half*)(smc + 2560);
    __half* qn_h  = (__half*)(smc + 7680);
    __half* vs0   = (__half*)(smc + 17920);
    __half* vs1   = (__half*)(smc + 52736);
    __half* pn_h  = (__half*)(smc + 87552);
    __half* wt_h  = vs0;                      // epilogue overlay
    __half* xm_h  = vs1;                      // epilogue overlay

    const int tid = threadIdx.x, w = tid >> 5, lane = tid & 31;
    const int row0 = (w & 3) * 32, col0 = (w >> 2) * 32;   // col0 in {0,32}
    const int qr = lane >> 2, ql = lane & 3;
    const int b = blockIdx.y, m0 = blockIdx.x * 64;
    const uint32_t qm_u = smem_u32(qm_h), qn_u = smem_u32(qn_h);
    const uint32_t vs0_u = smem_u32(vs0), vs1_u = smem_u32(vs1);
    const uint32_t pn_u = smem_u32(pn_h);
    const uint32_t wt_u = vs0_u, xm_u = vs1_u;
    const int la = ((lane >> 3) & 1) * 8 + (lane & 7);
    const int lc = (lane >> 4) * 8;
    const int lbr = (lane >> 4) * 8 + (lane & 7);
    const int lbc = ((lane >> 3) & 1) * 8;

    if (tid < 64) csum_s[tid] = 0.f;
    if (tid >= 64 && tid < 192) {
        int c = tid - 64;
        float A = gamma[c] * rsqrtf(var[c] + 1e-5f);
        A_s[c] = A;
        S_s[c] = beta[c] + (bt[c] - mean[c]) * A;
    }
    {   // qm: 64 rows x 32 halves
        int r = tid >> 2, j = (tid & 3) << 3;
        *(uint4*)&qm_h[r * 40 + j] =
            *(const uint4*)&g_qh[((size_t)b * NN + m0 + r) * DD + j];
    }
    // prologue prefetch: qn(0), vs(0) -> vs0
#pragma unroll
    for (int k = 0; k < 2; ++k) {
        int idx = tid + k * 256;
        int r = idx >> 2, j = (idx & 3) << 3;
        cpa16(qn_u + (r * 40 + j) * 2, &g_qh[((size_t)b * NN + r) * DD + j]);
    }
    CPA_COMMIT();
#pragma unroll
    for (int k = 0; k < 8; ++k) {
        int idx = tid + k * 256;
        int c = idx >> 4, j = (idx & 15) << 3;
        cpa16(vs0_u + (c * 136 + j) * 2, &g_v[((size_t)b * CC + c) * NN + j]);
    }
    CPA_COMMIT();

    float yacc[2][4][4] = {};
    float csum[8] = {};

    for (int nt = 0; nt < NN / 128; ++nt) {
        const int nb = nt * 128;
        const uint32_t vcur = (nt & 1) ? vs1_u : vs0_u;
        const uint32_t valt = (nt & 1) ? vs0_u : vs1_u;
        if (tid < 128) rl_s[tid] = g_rl[(size_t)b * NN + nb + tid];
        CPA_WAIT(1);                 // qn(nt) ready
        __syncthreads();             // sync1: qn+rl visible; prev Y done w/ pn

        // ---- E = qn . qm^T (fp16): warp 32x32 ----
        float e[2][4][4] = {};
#pragma unroll
        for (int ks = 0; ks < 2; ++ks) {
            const int k0 = ks * 16;
            uint32_t A[2][4], Bp[2][4];
#pragma unroll
            for (int mi = 0; mi < 2; ++mi)
                ldsm4(A[mi], qn_u + ((row0 + mi * 16 + la) * 40 + k0 + lc) * 2);
#pragma unroll
            for (int p = 0; p < 2; ++p)
                ldsm4(Bp[p], qm_u + ((col0 + p * 16 + lbr) * 40 + k0 + lbc) * 2);
#pragma unroll
            for (int mi = 0; mi < 2; ++mi)
#pragma unroll
                for (int ni = 0; ni < 4; ++ni)
                    mma16h(e[mi][ni], A[mi][0], A[mi][1], A[mi][2], A[mi][3],
                           Bp[ni >> 1][(ni & 1) * 2], Bp[ni >> 1][(ni & 1) * 2 + 1]);
        }

        // ---- p = exp2(e - rl[n]); csum; store [n][m] fp16 ----
#pragma unroll
        for (int mi = 0; mi < 2; ++mi) {
            int r = row0 + mi * 16 + qr;
            float rl0 = rl_s[r], rl1 = rl_s[r + 8];
#pragma unroll
            for (int ni = 0; ni < 4; ++ni) {
                int col = col0 + ni * 8 + 2 * ql;
                float p00 = ex2f(e[mi][ni][0] - rl0);
                float p01 = ex2f(e[mi][ni][1] - rl0);
                float p10 = ex2f(e[mi][ni][2] - rl1);
                float p11 = ex2f(e[mi][ni][3] - rl1);
                csum[ni * 2]     += p00 + p10;
                csum[ni * 2 + 1] += p01 + p11;
                *(half2*)&pn_h[r * 72 + col]       = __floats2half2_rn(p00, p01);
                *(half2*)&pn_h[(r + 8) * 72 + col] = __floats2half2_rn(p10, p11);
            }
        }
        CPA_WAIT(0);                 // vs(nt) ready
        __syncthreads();             // sync2: pn + vs visible; E done w/ qn

        if (nt + 1 < NN / 128) {     // prefetch qn(nt+1) + vs(nt+1) (alt buffer)
#pragma unroll
            for (int k = 0; k < 2; ++k) {
                int idx = tid + k * 256;
                int r = idx >> 2, j = (idx & 3) << 3;
                cpa16(qn_u + (r * 40 + j) * 2,
                      &g_qh[((size_t)b * NN + nb + 128 + r) * DD + j]);
            }
            CPA_COMMIT();
#pragma unroll
            for (int k = 0; k < 8; ++k) {
                int idx = tid + k * 256;
                int c = idx >> 4, j = (idx & 15) << 3;
                cpa16(valt + (c * 136 + j) * 2,
                      &g_v[((size_t)b * CC + c) * NN + nb + 128 + j]);
            }
            CPA_COMMIT();
        }

        // ---- Y += v @ p (fp16): warp 32x32, K=128 ----
#pragma unroll
        for (int ks = 0; ks < 8; ++ks) {
            const int k0 = ks * 16;
            uint32_t A[2][4], Bp[2][4];
#pragma unroll
            for (int mi = 0; mi < 2; ++mi)
                ldsm4(A[mi], vcur + ((row0 + mi * 16 + la) * 136 + k0 + lc) * 2);
#pragma unroll
            for (int p = 0; p < 2; ++p)
                ldsm4t(Bp[p], pn_u + ((k0 + la) * 72 + col0 + p * 16 + lc) * 2);
#pragma unroll
            for (int mi = 0; mi < 2; ++mi)
#pragma unroll
                for (int ni = 0; ni < 4; ++ni)
                    mma16h(yacc[mi][ni], A[mi][0], A[mi][1], A[mi][2], A[mi][3],
                           Bp[ni >> 1][(ni & 1) * 2], Bp[ni >> 1][(ni & 1) * 2 + 1]);
        }
        // no end barrier: sync1 of next iter orders pn reuse; vs is double-buffered
    }

    // ---------------- epilogue ----------------
#pragma unroll
    for (int i = 0; i < 8; ++i) {
        float v = csum[i];
        v += __shfl_xor_sync(0xffffffffu, v, 4);
        v += __shfl_xor_sync(0xffffffffu, v, 8);
        v += __shfl_xor_sync(0xffffffffu, v, 16);
        if (qr == 0) atomicAdd(&csum_s[col0 + (i >> 1) * 8 + 2 * ql + (i & 1)], v);
    }
    __syncthreads();   // (a): all Y done (vs0 free), csum complete
    if (tid < 64) cinv_s[tid] = 1.0f / (1e-9f + csum_s[tid]);
    // stage wt fp16 into vs0 region: [cout][cin] stride 136
    for (int i = tid; i < CC * 64; i += 256) {
        int co = i >> 6, cp = (i & 63) << 1;
        float2 wv2 = *(const float2*)&wt[co * CC + cp];
        *(half2*)&wt_h[co * 136 + cp] = __floats2half2_rn(wv2.x, wv2.y);
    }
    __syncthreads();   // (b): cinv visible

    // xm_h[m][c] = fp16(x - Y*cinv)
    const float* xb = x + ((size_t)b * CC) * NN + m0;
#pragma unroll
    for (int mi = 0; mi < 2; ++mi) {
        int r = row0 + mi * 16 + qr;
#pragma unroll
        for (int ni = 0; ni < 4; ++ni) {
            int col = col0 + ni * 8 + 2 * ql;
            float2 x0 = __ldg((const float2*)&xb[(size_t)r * NN + col]);
            float2 x1 = __ldg((const float2*)&xb[(size_t)(r + 8) * NN + col]);
            float ci0 = cinv_s[col], ci1 = cinv_s[col + 1];
            xm_h[col * 136 + r]           = __float2half_rn(x0.x - yacc[mi][ni][0] * ci0);
            xm_h[(col + 1) * 136 + r]     = __float2half_rn(x0.y - yacc[mi][ni][1] * ci1);
            xm_h[col * 136 + r + 8]       = __float2half_rn(x1.x - yacc[mi][ni][2] * ci0);
            xm_h[(col + 1) * 136 + r + 8] = __float2half_rn(x1.y - yacc[mi][ni][3] * ci1);
        }
    }
    __syncthreads();   // (c): wt_h + xm_h visible

    // t = wt @ xm  (fp16): A rows cout, B from xm_h [m][cin]
    float tacc[2][4][4] = {};
#pragma unroll
    for (int ks = 0; ks < 8; ++ks) {
        const int k0 = ks * 16;
        uint32_t A[2][4], Bp[2][4];
#pragma unroll
        for (int mi = 0; mi < 2; ++mi)
            ldsm4(A[mi], wt_u + ((row0 + mi * 16 + la) * 136 + k0 + lc) * 2);
#pragma unroll
        for (int p = 0; p < 2; ++p)
            ldsm4(Bp[p], xm_u + ((col0 + p * 16 + lbr) * 136 + k0 + lbc) * 2);
#pragma unroll
        for (int mi = 0; mi < 2; ++mi)
#pragma unroll
            for (int ni = 0; ni < 4; ++ni)
                mma16h(tacc[mi][ni], A[mi][0], A[mi][1], A[mi][2], A[mi][3],
                       Bp[ni >> 1][(ni & 1) * 2], Bp[ni >> 1][(ni & 1) * 2 + 1]);
    }

    // out = x + relu(t*A + S)
#pragma unroll
    for (int mi = 0; mi < 2; ++mi) {
        int r = row0 + mi * 16 + qr;
        float a0 = A_s[r], s0 = S_s[r];
        float a1 = A_s[r + 8], s1 = S_s[r + 8];
#pragma unroll
        for (int ni = 0; ni < 4; ++ni) {
            int col = col0 + ni * 8 + 2 * ql;
            float2 x0 = __ldg((const float2*)&xb[(size_t)r * NN + col]);
            float2 x1 = __ldg((const float2*)&xb[(size_t)(r + 8) * NN + col]);
            float2 o0, o1;
            o0.x = x0.x + fmaxf(fmaf(tacc[mi][ni][0], a0, s0), 0.f);
            o0.y = x0.y + fmaxf(fmaf(tacc[mi][ni][1], a0, s0), 0.f);
            o1.x = x1.x + fmaxf(fmaf(tacc[mi][ni][2], a1, s1), 0.f);
            o1.y = x1.y + fmaxf(fmaf(tacc[mi][ni][3], a1, s1), 0.f);
            *(float2*)&out[((size_t)b * CC + r) * NN + m0 + col]     = o0;
            *(float2*)&out[((size_t)b * CC + r + 8) * NN + m0 + col] = o1;
        }
    }
}

// ======================================================================
extern "C" void kernel_launch(void* const* d_in, const int* in_sizes, int n_in,
                              void* d_out, int out_size) {
    const float* x     = (const float*)d_in[0];
    const float* wq    = (const float*)d_in[1];
    const float* wv    = (const float*)d_in[2];
    const float* bv    = (const float*)d_in[3];
    const float* wt    = (const float*)d_in[4];
    const float* bt    = (const float*)d_in[5];
    const float* gamma = (const float*)d_in[6];
    const float* beta  = (const float*)d_in[7];
    const float* mean  = (const float*)d_in[8];
    const float* var   = (const float*)d_in[9];
    float* out = (float*)d_out;

    const int S1 = 95360;
    const int S2 = 128 * 4 + 3 * 128 * 40 * 2;   // 31232
    const int S3 = 105984;

    cudaFuncSetAttribute(k_qv,     cudaFuncAttributeMaxDynamicSharedMemorySize, S1);
    cudaFuncSetAttribute(k_rowsum, cudaFuncAttributeMaxDynamicSharedMemorySize, S2);
    cudaFuncSetAttribute(k_attn,   cudaFuncAttributeMaxDynamicSharedMemorySize, S3);

    k_qv<<<dim3(16, 16), 640, S1>>>(x, wq, wv, bv);
    k_rowsum<<<dim3(16, 16), 512, S2>>>();
    k_attn<<<dim3(32, 16), 256, S3>>>(x, wt, bt, gamma, beta, mean, var, out);
}

// round 11
// speedup vs baseline: 1.9161x; 1.0272x over previous
#include <cuda_runtime.h>
#include <cuda_fp16.h>
#include <cstdint>

#define BB 16
#define CC 128
#define DD 32
#define NN 2048
#define SQRT_LOG2E 1.2011224087864498f

// ---------------- device scratch (static) ----------------
__device__ __half g_qh[BB * NN * DD];   // qT[b][n][d], *sqrt(log2e), fp16
__device__ __half g_v [BB * CC * NN];   // v[b][c][n], fp16
__device__ float  g_rl[BB * NN];        // log2(rowsum)

// ---------------- helpers ----------------
__device__ __forceinline__ float ex2f(float x) {
    float y; asm("ex2.approx.ftz.f32 %0, %1;" : "=f"(y) : "f"(x)); return y;
}
__device__ __forceinline__ float lg2f(float x) {
    float y; asm("lg2.approx.f32 %0, %1;" : "=f"(y) : "f"(x)); return y;
}
__device__ __forceinline__ void mma16h(float c[4],
                                       uint32_t a0, uint32_t a1, uint32_t a2, uint32_t a3,
                                       uint32_t b0, uint32_t b1) {
    asm volatile(
        "mma.sync.aligned.m16n8k16.row.col.f32.f16.f16.f32 "
        "{%0,%1,%2,%3}, {%4,%5,%6,%7}, {%8,%9}, {%0,%1,%2,%3};"
        : "+f"(c[0]), "+f"(c[1]), "+f"(c[2]), "+f"(c[3])
        : "r"(a0), "r"(a1), "r"(a2), "r"(a3), "r"(b0), "r"(b1));
}
__device__ __forceinline__ void ldsm4(uint32_t r[4], uint32_t addr) {
    asm volatile("ldmatrix.sync.aligned.m8n8.x4.shared.b16 {%0,%1,%2,%3}, [%4];"
        : "=r"(r[0]), "=r"(r[1]), "=r"(r[2]), "=r"(r[3]) : "r"(addr));
}
__device__ __forceinline__ void ldsm4t(uint32_t r[4], uint32_t addr) {
    asm volatile("ldmatrix.sync.aligned.m8n8.x4.trans.shared.b16 {%0,%1,%2,%3}, [%4];"
        : "=r"(r[0]), "=r"(r[1]), "=r"(r[2]), "=r"(r[3]) : "r"(addr));
}
__device__ __forceinline__ uint32_t smem_u32(const void* p) {
    uint32_t a;
    asm("{ .reg .u64 t; cvta.to.shared.u64 t, %1; cvt.u32.u64 %0, t; }" : "=r"(a) : "l"(p));
    return a;
}
__device__ __forceinline__ void cpa16(uint32_t dst, const void* src) {
    asm volatile("cp.async.cg.shared.global [%0], [%1], 16;" :: "r"(dst), "l"(src));
}
#define CPA_COMMIT() asm volatile("cp.async.commit_group;" ::: "memory")
#define CPA_WAIT(n)  asm volatile("cp.async.wait_group %0;" :: "n"(n) : "memory")

// ======================================================================
// k1: q = wq@x (scaled, fp16) ; v = wv@x + bv (fp16) — fp16 mma compute
// (R9 version — measured 26us; R10's staging rework regressed and is reverted)
// 640 threads (20 warps, 32x32 warp tiles on a 160x128 output).
// ======================================================================
__global__ __launch_bounds__(640) void k_qv(const float* __restrict__ x,
                                            const float* __restrict__ wq,
                                            const float* __restrict__ wv,
                                            const float* __restrict__ bv) {
    extern __shared__ char smc[];
    __half* xh   = (__half*)smc;              // [n][c] stride 136
    __half* wsh  = (__half*)(smc + 34816);    // [r][c] stride 136
    float*  qb   = (float*)(smc + 78336);     // 32x129
    float*  bv_s = (float*)(smc + 94848);
    const int b  = blockIdx.y;
    const int n0 = blockIdx.x * 128;
    const int tid = threadIdx.x;
    const float* xb = x + (size_t)b * CC * NN;

    for (int i = tid; i < CC * 128; i += 640) {
        int c = i >> 7, n = i & 127;
        xh[n * 136 + c] = __float2half_rn(xb[(size_t)c * NN + n0 + n]);
    }
    for (int i = tid; i < 160 * 128; i += 640) {
        int r = i >> 7, c = i & 127;
        float w = (r < DD) ? wq[r * CC + c] : wv[(r - DD) * CC + c];
        wsh[r * 136 + c] = __float2half_rn(w);
    }
    if (tid < CC) bv_s[tid] = bv[tid];
    __syncthreads();

    const int w = tid >> 5, lane = tid & 31;
    const int rg = w >> 2, cg = w & 3;
    const int row0 = rg * 32, col0 = cg * 32;
    const int qr = lane >> 2, ql = lane & 3;
    const uint32_t ws_u = smem_u32(wsh), xh_u = smem_u32(xh);
    const int la = ((lane >> 3) & 1) * 8 + (lane & 7);
    const int lc = (lane >> 4) * 8;
    const int lbr = (lane >> 4) * 8 + (lane & 7);
    const int lbc = ((lane >> 3) & 1) * 8;

    float acc[2][4][4] = {};
#pragma unroll
    for (int ks = 0; ks < 8; ++ks) {
        const int k0 = ks * 16;
        uint32_t A[2][4], Bp[2][4];
#pragma unroll
        for (int mi = 0; mi < 2; ++mi)
            ldsm4(A[mi], ws_u + ((row0 + mi * 16 + la) * 136 + k0 + lc) * 2);
#pragma unroll
        for (int p = 0; p < 2; ++p)
            ldsm4(Bp[p], xh_u + ((col0 + p * 16 + lbr) * 136 + k0 + lbc) * 2);
#pragma unroll
        for (int mi = 0; mi < 2; ++mi)
#pragma unroll
            for (int ni = 0; ni < 4; ++ni)
                mma16h(acc[mi][ni], A[mi][0], A[mi][1], A[mi][2], A[mi][3],
                       Bp[ni >> 1][(ni & 1) * 2], Bp[ni >> 1][(ni & 1) * 2 + 1]);
    }

    if (rg == 0) {
#pragma unroll
        for (int mi = 0; mi < 2; ++mi) {
            int d = mi * 16 + qr;
#pragma unroll
            for (int ni = 0; ni < 4; ++ni) {
                int col = col0 + ni * 8 + 2 * ql;
                qb[d * 129 + col]           = acc[mi][ni][0] * SQRT_LOG2E;
                qb[d * 129 + col + 1]       = acc[mi][ni][1] * SQRT_LOG2E;
                qb[(d + 8) * 129 + col]     = acc[mi][ni][2] * SQRT_LOG2E;
                qb[(d + 8) * 129 + col + 1] = acc[mi][ni][3] * SQRT_LOG2E;
            }
        }
    } else {
#pragma unroll
        for (int mi = 0; mi < 2; ++mi) {
            int rv = row0 - DD + mi * 16 + qr;
            float b0v = bv_s[rv], b1v = bv_s[rv + 8];
#pragma unroll
            for (int ni = 0; ni < 4; ++ni) {
                int col = col0 + ni * 8 + 2 * ql;
                *(half2*)&g_v[((size_t)b * CC + rv) * NN + n0 + col] =
                    __floats2half2_rn(acc[mi][ni][0] + b0v, acc[mi][ni][1] + b0v);
                *(half2*)&g_v[((size_t)b * CC + rv + 8) * NN + n0 + col] =
                    __floats2half2_rn(acc[mi][ni][2] + b1v, acc[mi][ni][3] + b1v);
            }
        }
    }
    __syncthreads();
    for (int i = tid; i < 128 * 16; i += 640) {
        int n = i >> 4, d2 = (i & 15) << 1;
        *(half2*)&g_qh[((size_t)b * NN + n0 + n) * DD + d2] =
            __floats2half2_rn(qb[d2 * 129 + n], qb[(d2 + 1) * 129 + n]);
    }
}

// ======================================================================
// k2: rl[n] = log2( sum_m exp2(E[n,m]) ), fp16 mma + ldmatrix.
// 512 threads, 2 CTAs/SM, double-buffered qm via cp.async.  (unchanged)
// ======================================================================
__global__ __launch_bounds__(512, 2) void k_rowsum() {
    extern __shared__ float sm[];
    float*  red  = sm;
    __half* qn_h = (__half*)(sm + 128);
    __half* qm0  = qn_h + 128 * 40;
    __half* qm1  = qm0 + 128 * 40;

    const int tid = threadIdx.x, w = tid >> 5, lane = tid & 31;
    const int row0 = (w & 3) * 32, col0 = (w >> 2) * 32;
    const int b = blockIdx.y, n0 = blockIdx.x * 128;
    const uint32_t qn_u = smem_u32(qn_h), qm0u = smem_u32(qm0), qm1u = smem_u32(qm1);
    const int la = ((lane >> 3) & 1) * 8 + (lane & 7);
    const int lc = (lane >> 4) * 8;
    const int lbr = (lane >> 4) * 8 + (lane & 7);
    const int lbc = ((lane >> 3) & 1) * 8;

    if (tid < 128) red[tid] = 0.f;
    {
        int r = tid >> 2, j = (tid & 3) << 3;
        cpa16(qn_u + (r * 40 + j) * 2, &g_qh[((size_t)b * NN + n0 + r) * DD + j]);
    }
    CPA_COMMIT();
    {
        int r = tid >> 2, j = (tid & 3) << 3;
        cpa16(qm0u + (r * 40 + j) * 2, &g_qh[((size_t)b * NN + r) * DD + j]);
    }
    CPA_COMMIT();

    float racc[2][2] = {};
    for (int mt = 0; mt < NN / 128; ++mt) {
        const uint32_t qmu = (mt & 1) ? qm1u : qm0u;
        const uint32_t qmnu = (mt & 1) ? qm0u : qm1u;
        CPA_WAIT(0);
        __syncthreads();
        if (mt + 1 < NN / 128) {
            int r = tid >> 2, j = (tid & 3) << 3;
            cpa16(qmnu + (r * 40 + j) * 2,
                  &g_qh[((size_t)b * NN + (mt + 1) * 128 + r) * DD + j]);
            CPA_COMMIT();
        }

        float e[2][4][4] = {};
#pragma unroll
        for (int ks = 0; ks < 2; ++ks) {
            const int k0 = ks * 16;
            uint32_t A[2][4], Bp[2][4];
#pragma unroll
            for (int mi = 0; mi < 2; ++mi)
                ldsm4(A[mi], qn_u + ((row0 + mi * 16 + la) * 40 + k0 + lc) * 2);
#pragma unroll
            for (int p = 0; p < 2; ++p)
                ldsm4(Bp[p], qmu + ((col0 + p * 16 + lbr) * 40 + k0 + lbc) * 2);
#pragma unroll
            for (int mi = 0; mi < 2; ++mi)
#pragma unroll
                for (int ni = 0; ni < 4; ++ni)
                    mma16h(e[mi][ni], A[mi][0], A[mi][1], A[mi][2], A[mi][3],
                           Bp[ni >> 1][(ni & 1) * 2], Bp[ni >> 1][(ni & 1) * 2 + 1]);
        }
#pragma unroll
        for (int mi = 0; mi < 2; ++mi)
#pragma unroll
            for (int ni = 0; ni < 4; ++ni) {
                racc[mi][0] += ex2f(e[mi][ni][0]) + ex2f(e[mi][ni][1]);
                racc[mi][1] += ex2f(e[mi][ni][2]) + ex2f(e[mi][ni][3]);
            }
    }

    const int qr = lane >> 2, ql = lane & 3;
#pragma unroll
    for (int mi = 0; mi < 2; ++mi)
#pragma unroll
        for (int h = 0; h < 2; ++h) {
            float v = racc[mi][h];
            v += __shfl_xor_sync(0xffffffffu, v, 1);
            v += __shfl_xor_sync(0xffffffffu, v, 2);
            racc[mi][h] = v;
        }
    if (ql == 0) {
        atomicAdd(&red[row0 + qr],          racc[0][0]);
        atomicAdd(&red[row0 + qr + 8],      racc[0][1]);
        atomicAdd(&red[row0 + 16 + qr],     racc[1][0]);
        atomicAdd(&red[row0 + 16 + qr + 8], racc[1][1]);
    }
    __syncthreads();
    if (tid < 128) g_rl[(size_t)b * NN + n0 + tid] = lg2f(red[tid]);
}

// ======================================================================
// k3: fused attention + epilogue. 256 threads, m-tile 64, n-tile 128,
// 2 CTAs/SM. vs + rl double-buffered; prefetch of vs/rl issued at sync1
// (full-iteration cover), qn at sync2. One CPA_WAIT per iteration.
// smem bytes:
//   header @0 (3584): csum 64f, cinv 64f, A_s 128f, S_s 128f, rl0 128f, rl1 128f
//   qm_h @3584  (64x40 h  = 5120)
//   qn_h @8704  (128x40 h = 10240)
//   vs0  @18944 (128x136 h = 34816)   epi overlay: wt_h [cout][cin] str 136
//   vs1  @53760 (34816)               epi overlay: xm_h [m][c] str 136
//   pn_h @88576 (128x72 h = 18432)
//   total 107008 B  (2 CTAs/SM)
// ======================================================================
__global__ __launch_bounds__(256, 2) void k_attn(const float* __restrict__ x,
                                                 const float* __restrict__ wt,
                                                 const float* __restrict__ bt,
                                                 const float* __restrict__ gamma,
                                                 const float* __restrict__ beta,
                                                 const float* __restrict__ mean,
                                                 const float* __restrict__ var,
                                                 float* __restrict__ out) {
    extern __shared__ float sm[];
    char* smc = (char*)sm;
    float* csum_s = sm;             // 64
    float* cinv_s = sm + 64;        // 64
    float* A_s    = sm + 128;       // 128
    float* S_s    = sm + 256;       // 128
    float* rl0_s  = sm + 384;       // 128
    float* rl1_s  = sm + 512;       // 128
    __half* qm_h  = (__half*)(smc + 3584);
    __half* qn_h  = (__half*)(smc + 8704);
    __half* vs0   = (__half*)(smc + 18944);
    __half* vs1   = (__half*)(smc + 53760);
    __half* pn_h  = (__half*)(smc + 88576);
    __half* wt_h  = vs0;                      // epilogue overlay
    __half* xm_h  = vs1;                      // epilogue overlay

    const int tid = threadIdx.x, w = tid >> 5, lane = tid & 31;
    const int row0 = (w & 3) * 32, col0 = (w >> 2) * 32;   // col0 in {0,32}
    const int qr = lane >> 2, ql = lane & 3;
    const int b = blockIdx.y, m0 = blockIdx.x * 64;
    const uint32_t qm_u = smem_u32(qm_h), qn_u = smem_u32(qn_h);
    const uint32_t vs0_u = smem_u32(vs0), vs1_u = smem_u32(vs1);
    const uint32_t pn_u = smem_u32(pn_h);
    const uint32_t rl0_u = smem_u32(rl0_s), rl1_u = smem_u32(rl1_s);
    const uint32_t wt_u = vs0_u, xm_u = vs1_u;
    const int la = ((lane >> 3) & 1) * 8 + (lane & 7);
    const int lc = (lane >> 4) * 8;
    const int lbr = (lane >> 4) * 8 + (lane & 7);
    const int lbc = ((lane >> 3) & 1) * 8;
    const float* grl = &g_rl[(size_t)b * NN];

    if (tid < 64) csum_s[tid] = 0.f;
    if (tid >= 64 && tid < 192) {
        int c = tid - 64;
        float A = gamma[c] * rsqrtf(var[c] + 1e-5f);
        A_s[c] = A;
        S_s[c] = beta[c] + (bt[c] - mean[c]) * A;
    }
    {   // qm: 64 rows x 32 halves
        int r = tid >> 2, j = (tid & 3) << 3;
        *(uint4*)&qm_h[r * 40 + j] =
            *(const uint4*)&g_qh[((size_t)b * NN + m0 + r) * DD + j];
    }
    // prologue: G1 = vs(0)->vs0 + rl(0)->rl0 ; G2 = qn(0)
#pragma unroll
    for (int k = 0; k < 8; ++k) {
        int idx = tid + k * 256;
        int c = idx >> 4, j = (idx & 15) << 3;
        cpa16(vs0_u + (c * 136 + j) * 2, &g_v[((size_t)b * CC + c) * NN + j]);
    }
    if (tid < 32) cpa16(rl0_u + tid * 16, grl + tid * 4);
    CPA_COMMIT();
#pragma unroll
    for (int k = 0; k < 2; ++k) {
        int idx = tid + k * 256;
        int r = idx >> 2, j = (idx & 3) << 3;
        cpa16(qn_u + (r * 40 + j) * 2, &g_qh[((size_t)b * NN + r) * DD + j]);
    }
    CPA_COMMIT();

    float yacc[2][4][4] = {};
    float csum[8] = {};

    for (int nt = 0; nt < NN / 128; ++nt) {
        const int nb = nt * 128;
        const uint32_t vcur = (nt & 1) ? vs1_u : vs0_u;
        const uint32_t valt = (nt & 1) ? vs0_u : vs1_u;
        const float*   rlc  = (nt & 1) ? rl1_s : rl0_s;
        const uint32_t rla  = (nt & 1) ? rl0_u : rl1_u;
        CPA_WAIT(0);                 // qn(nt), vs(nt), rl(nt) all ready
        __syncthreads();             // sync1: loads visible; prev Y done w/ pn

        // prefetch vs(nt+1) + rl(nt+1) — full-iteration cover (valt/rl-alt free)
        if (nt + 1 < NN / 128) {
#pragma unroll
            for (int k = 0; k < 8; ++k) {
                int idx = tid + k * 256;
                int c = idx >> 4, j = (idx & 15) << 3;
                cpa16(valt + (c * 136 + j) * 2,
                      &g_v[((size_t)b * CC + c) * NN + nb + 128 + j]);
            }
            if (tid < 32) cpa16(rla + tid * 16, grl + nb + 128 + tid * 4);
            CPA_COMMIT();
        }

        // ---- E = qn . qm^T (fp16): warp 32x32 ----
        float e[2][4][4] = {};
#pragma unroll
        for (int ks = 0; ks < 2; ++ks) {
            const int k0 = ks * 16;
            uint32_t A[2][4], Bp[2][4];
#pragma unroll
            for (int mi = 0; mi < 2; ++mi)
                ldsm4(A[mi], qn_u + ((row0 + mi * 16 + la) * 40 + k0 + lc) * 2);
#pragma unroll
            for (int p = 0; p < 2; ++p)
                ldsm4(Bp[p], qm_u + ((col0 + p * 16 + lbr) * 40 + k0 + lbc) * 2);
#pragma unroll
            for (int mi = 0; mi < 2; ++mi)
#pragma unroll
                for (int ni = 0; ni < 4; ++ni)
                    mma16h(e[mi][ni], A[mi][0], A[mi][1], A[mi][2], A[mi][3],
                           Bp[ni >> 1][(ni & 1) * 2], Bp[ni >> 1][(ni & 1) * 2 + 1]);
        }

        // ---- p = exp2(e - rl[n]); csum; store [n][m] fp16 ----
#pragma unroll
        for (int mi = 0; mi < 2; ++mi) {
            int r = row0 + mi * 16 + qr;
            float rlv0 = rlc[r], rlv1 = rlc[r + 8];
#pragma unroll
            for (int ni = 0; ni < 4; ++ni) {
                int col = col0 + ni * 8 + 2 * ql;
                float p00 = ex2f(e[mi][ni][0] - rlv0);
                float p01 = ex2f(e[mi][ni][1] - rlv0);
                float p10 = ex2f(e[mi][ni][2] - rlv1);
                float p11 = ex2f(e[mi][ni][3] - rlv1);
                csum[ni * 2]     += p00 + p10;
                csum[ni * 2 + 1] += p01 + p11;
                *(half2*)&pn_h[r * 72 + col]       = __floats2half2_rn(p00, p01);
                *(half2*)&pn_h[(r + 8) * 72 + col] = __floats2half2_rn(p10, p11);
            }
        }
        __syncthreads();             // sync2: pn visible; E done w/ qn

        if (nt + 1 < NN / 128) {     // prefetch qn(nt+1) — Y-phase cover
#pragma unroll
            for (int k = 0; k < 2; ++k) {
                int idx = tid + k * 256;
                int r = idx >> 2, j = (idx & 3) << 3;
                cpa16(qn_u + (r * 40 + j) * 2,
                      &g_qh[((size_t)b * NN + nb + 128 + r) * DD + j]);
            }
            CPA_COMMIT();
        }

        // ---- Y += v @ p (fp16): warp 32x32, K=128 ----
#pragma unroll
        for (int ks = 0; ks < 8; ++ks) {
            const int k0 = ks * 16;
            uint32_t A[2][4], Bp[2][4];
#pragma unroll
            for (int mi = 0; mi < 2; ++mi)
                ldsm4(A[mi], vcur + ((row0 + mi * 16 + la) * 136 + k0 + lc) * 2);
#pragma unroll
            for (int p = 0; p < 2; ++p)
                ldsm4t(Bp[p], pn_u + ((k0 + la) * 72 + col0 + p * 16 + lc) * 2);
#pragma unroll
            for (int mi = 0; mi < 2; ++mi)
#pragma unroll
                for (int ni = 0; ni < 4; ++ni)
                    mma16h(yacc[mi][ni], A[mi][0], A[mi][1], A[mi][2], A[mi][3],
                           Bp[ni >> 1][(ni & 1) * 2], Bp[ni >> 1][(ni & 1) * 2 + 1]);
        }
        // no end barrier: sync1 of next iter orders pn reuse; vs/rl double-buffered
    }

    // ---------------- epilogue ----------------
#pragma unroll
    for (int i = 0; i < 8; ++i) {
        float v = csum[i];
        v += __shfl_xor_sync(0xffffffffu, v, 4);
        v += __shfl_xor_sync(0xffffffffu, v, 8);
        v += __shfl_xor_sync(0xffffffffu, v, 16);
        if (qr == 0) atomicAdd(&csum_s[col0 + (i >> 1) * 8 + 2 * ql + (i & 1)], v);
    }
    __syncthreads();   // all Y done (vs free), csum complete
    if (tid < 64) cinv_s[tid] = 1.0f / (1e-9f + csum_s[tid]);
    // stage wt fp16 into vs0 region: [cout][cin] stride 136
    for (int i = tid; i < CC * 64; i += 256) {
        int co = i >> 6, cp = (i & 63) << 1;
        float2 wv2 = *(const float2*)&wt[co * CC + cp];
        *(half2*)&wt_h[co * 136 + cp] = __floats2half2_rn(wv2.x, wv2.y);
    }
    __syncthreads();   // cinv visible

    // xm_h[m][c] = fp16(x - Y*cinv)
    const float* xb = x + ((size_t)b * CC) * NN + m0;
#pragma unroll
    for (int mi = 0; mi < 2; ++mi) {
        int r = row0 + mi * 16 + qr;
#pragma unroll
        for (int ni = 0; ni < 4; ++ni) {
            int col = col0 + ni * 8 + 2 * ql;
            float2 x0 = __ldg((const float2*)&xb[(size_t)r * NN + col]);
            float2 x1 = __ldg((const float2*)&xb[(size_t)(r + 8) * NN + col]);
            float ci0 = cinv_s[col], ci1 = cinv_s[col + 1];
            xm_h[col * 136 + r]           = __float2half_rn(x0.x - yacc[mi][ni][0] * ci0);
            xm_h[(col + 1) * 136 + r]     = __float2half_rn(x0.y - yacc[mi][ni][1] * ci1);
            xm_h[col * 136 + r + 8]       = __float2half_rn(x1.x - yacc[mi][ni][2] * ci0);
            xm_h[(col + 1) * 136 + r + 8] = __float2half_rn(x1.y - yacc[mi][ni][3] * ci1);
        }
    }
    __syncthreads();   // wt_h + xm_h visible

    // t = wt @ xm  (fp16)
    float tacc[2][4][4] = {};
#pragma unroll
    for (int ks = 0; ks < 8; ++ks) {
        const int k0 = ks * 16;
        uint32_t A[2][4], Bp[2][4];
#pragma unroll
        for (int mi = 0; mi < 2; ++mi)
            ldsm4(A[mi], wt_u + ((row0 + mi * 16 + la) * 136 + k0 + lc) * 2);
#pragma unroll
        for (int p = 0; p < 2; ++p)
            ldsm4(Bp[p], xm_u + ((col0 + p * 16 + lbr) * 136 + k0 + lbc) * 2);
#pragma unroll
        for (int mi = 0; mi < 2; ++mi)
#pragma unroll
            for (int ni = 0; ni < 4; ++ni)
                mma16h(tacc[mi][ni], A[mi][0], A[mi][1], A[mi][2], A[mi][3],
                       Bp[ni >> 1][(ni & 1) * 2], Bp[ni >> 1][(ni & 1) * 2 + 1]);
    }

    // out = x + relu(t*A + S)
#pragma unroll
    for (int mi = 0; mi < 2; ++mi) {
        int r = row0 + mi * 16 + qr;
        float a0 = A_s[r], s0 = S_s[r];
        float a1 = A_s[r + 8], s1 = S_s[r + 8];
#pragma unroll
        for (int ni = 0; ni < 4; ++ni) {
            int col = col0 + ni * 8 + 2 * ql;
            float2 x0 = __ldg((const float2*)&xb[(size_t)r * NN + col]);
            float2 x1 = __ldg((const float2*)&xb[(size_t)(r + 8) * NN + col]);
            float2 o0, o1;
            o0.x = x0.x + fmaxf(fmaf(tacc[mi][ni][0], a0, s0), 0.f);
            o0.y = x0.y + fmaxf(fmaf(tacc[mi][ni][1], a0, s0), 0.f);
            o1.x = x1.x + fmaxf(fmaf(tacc[mi][ni][2], a1, s1), 0.f);
            o1.y = x1.y + fmaxf(fmaf(tacc[mi][ni][3], a1, s1), 0.f);
            *(float2*)&out[((size_t)b * CC + r) * NN + m0 + col]     = o0;
            *(float2*)&out[((size_t)b * CC + r + 8) * NN + m0 + col] = o1;
        }
    }
}

// ======================================================================
extern "C" void kernel_launch(void* const* d_in, const int* in_sizes, int n_in,
                              void* d_out, int out_size) {
    const float* x     = (const float*)d_in[0];
    const float* wq    = (const float*)d_in[1];
    const float* wv    = (const float*)d_in[2];
    const float* bv    = (const float*)d_in[3];
    const float* wt    = (const float*)d_in[4];
    const float* bt    = (const float*)d_in[5];
    const float* gamma = (const float*)d_in[6];
    const float* beta  = (const float*)d_in[7];
    const float* mean  = (const float*)d_in[8];
    const float* var   = (const float*)d_in[9];
    float* out = (float*)d_out;

    const int S1 = 95360;
    const int S2 = 128 * 4 + 3 * 128 * 40 * 2;   // 31232
    const int S3 = 107008;

    cudaFuncSetAttribute(k_qv,     cudaFuncAttributeMaxDynamicSharedMemorySize, S1);
    cudaFuncSetAttribute(k_rowsum, cudaFuncAttributeMaxDynamicSharedMemorySize, S2);
    cudaFuncSetAttribute(k_attn,   cudaFuncAttributeMaxDynamicSharedMemorySize, S3);

    k_qv<<<dim3(16, 16), 640, S1>>>(x, wq, wv, bv);
    k_rowsum<<<dim3(16, 16), 512, S2>>>();
    k_attn<<<dim3(32, 16), 256, S3>>>(x, wt, bt, gamma, beta, mean, var, out);
}